// round 12
// baseline (speedup 1.0000x reference)
#include <cuda_runtime.h>
#include <cuda_fp16.h>
#include <math.h>
#include <stdint.h>

// ---------------------------------------------------------------------------
// SRU, 2 layers. Legacy mma.sync HMMA (base sm_103 target; no tcgen05).
// Split-fp16 3-term GEMM: Y = Ahi*Bhi (fp32 acc) + [Ahi*Blo + Alo*Bhi] (fp16 acc)
// R12: lo-terms use f16-accumulator MMA (rated 2x of f32-acc) -> 2/3 of MMAs
//      run at double rate. BM=BN=128, BK=32, 8 warps (64x32), 3-stage.
// ---------------------------------------------------------------------------

#define T_STEPS 512
#define BATCH   32
#define NIN     1024
#define NOUT    512
#define M_TOT   16384
#define NBIG    2048
#define E_TOT   16384

__device__ __align__(256) float  g_Y[(size_t)M_TOT * NBIG];
__device__ __align__(256) __half g_xhi[(size_t)M_TOT * NIN];
__device__ __align__(256) __half g_xlo[(size_t)M_TOT * NIN];
__device__ __align__(256) __half g_h1hi[(size_t)M_TOT * NOUT];
__device__ __align__(256) __half g_h1lo[(size_t)M_TOT * NOUT];
__device__ __align__(256) __half g_hchi[(size_t)M_TOT * NIN];
__device__ __align__(256) __half g_hclo[(size_t)M_TOT * NIN];
__device__ __align__(256) __half g_whi[(size_t)NBIG * NIN];
__device__ __align__(256) __half g_wlo[(size_t)NBIG * NIN];
__device__ __align__(256) __half g_wxlhi[(size_t)NIN * NOUT];
__device__ __align__(256) __half g_wxllo[(size_t)NIN * NOUT];
__device__ __align__(256) float  g_bias[NBIG];

// ---------------------------------------------------------------------------
__device__ __forceinline__ uint32_t smem_u32(const void* p) {
    uint32_t a;
    asm("{ .reg .u64 t; cvta.to.shared.u64 t, %1; cvt.u32.u64 %0, t; }"
        : "=r"(a) : "l"(p));
    return a;
}
__device__ __forceinline__ void cp16(uint32_t d, const void* s) {
    asm volatile("cp.async.cg.shared.global [%0], [%1], 16;"
                 :: "r"(d), "l"(s) : "memory");
}
__device__ __forceinline__ void cp_commit() {
    asm volatile("cp.async.commit_group;" ::: "memory");
}
__device__ __forceinline__ void cp_wait1() {
    asm volatile("cp.async.wait_group 1;" ::: "memory");
}
__device__ __forceinline__ void ldsm4(uint32_t* r, uint32_t a) {
    asm volatile("ldmatrix.sync.aligned.m8n8.x4.shared.b16 {%0,%1,%2,%3}, [%4];"
                 : "=r"(r[0]), "=r"(r[1]), "=r"(r[2]), "=r"(r[3]) : "r"(a));
}
__device__ __forceinline__ void mma16816(float* c, const uint32_t* a,
                                         const uint32_t* b) {
    asm volatile(
        "mma.sync.aligned.m16n8k16.row.col.f32.f16.f16.f32 "
        "{%0,%1,%2,%3}, {%4,%5,%6,%7}, {%8,%9}, {%0,%1,%2,%3};"
        : "+f"(c[0]), "+f"(c[1]), "+f"(c[2]), "+f"(c[3])
        : "r"(a[0]), "r"(a[1]), "r"(a[2]), "r"(a[3]), "r"(b[0]), "r"(b[1]));
}
// fp16-accumulator variant (rated 2x throughput of f32-acc on the HMMA pipe)
__device__ __forceinline__ void mma16816h(uint32_t* c, const uint32_t* a,
                                          const uint32_t* b) {
    asm volatile(
        "mma.sync.aligned.m16n8k16.row.col.f16.f16.f16.f16 "
        "{%0,%1}, {%2,%3,%4,%5}, {%6,%7}, {%0,%1};"
        : "+r"(c[0]), "+r"(c[1])
        : "r"(a[0]), "r"(a[1]), "r"(a[2]), "r"(a[3]), "r"(b[0]), "r"(b[1]));
}

// ---------------------------------------------------------------------------
// GEMM: Y[M,N] = Ahi*Bhi^T (f32 acc) + Ahi*Blo^T + Alo*Bhi^T (f16 acc)
// BM=128 BN=128 BK=32, 256 threads (8 warps: 2m x 4n, warp 64x32),
// 3-stage cp.async, single __syncthreads per stage.
// Smem rows 80B (odd 16B stride -> conflict-free ldmatrix).
// MODE 0: fp32 out + g_bias + sigmoid on n in [512,1536)
// MODE 1: fp16 hi/lo out + fp32 bias vector
// ---------------------------------------------------------------------------
#define ROWB        80
#define SLAB        (128 * ROWB)            // 10240 B (one 128x32-half tile)
#define STAGE_BYTES (4 * SLAB)              // 40960 B (Ahi|Alo|Bhi|Blo)
#define GEMM_SMEM   (3 * STAGE_BYTES)       // 122880 B

template <int MODE>
__global__ __launch_bounds__(256, 1)
void gemm_tc(const __half* __restrict__ Ahi, const __half* __restrict__ Alo,
             const __half* __restrict__ Bhi, const __half* __restrict__ Blo,
             const float* __restrict__ bias,
             float* __restrict__ Yf,
             __half* __restrict__ Yhi, __half* __restrict__ Ylo,
             int K, int ldy)
{
    extern __shared__ __align__(128) char smem_dyn[];
    const uint32_t sb0 = smem_u32(smem_dyn);

    const int tid  = threadIdx.x;
    const int lane = tid & 31;
    const int wid  = tid >> 5;               // 0..7
    const int m_warp = (wid >> 2) * 64;      // 0,64
    const int n_warp = (wid & 3) * 32;       // 0..96
    const int mb = blockIdx.y * 128;
    const int nb = blockIdx.x * 128;

    // ldmatrix lane addressing
    const int a_row  = m_warp + (lane & 15);
    const int a_coff = (lane >> 4) * 16;
    const int b_t    = lane >> 3;
    const int b_row  = n_warp + (b_t >> 1) * 8 + (lane & 7);
    const int b_coff = (b_t & 1) * 16;

    float acc[4][4][4];            // main term, fp32
    uint32_t acch[4][4][2];        // lo terms, fp16 (half2 pairs)
    #pragma unroll
    for (int i = 0; i < 4; i++)
        #pragma unroll
        for (int j = 0; j < 4; j++) {
            #pragma unroll
            for (int q = 0; q < 4; q++) acc[i][j][q] = 0.f;
            acch[i][j][0] = 0u; acch[i][j][1] = 0u;
        }

    // cp.async mapping: per slab 512 16B chunks (128 rows x 4), 2 per thread
    const int ld_col = tid & 3;
    const int ld_r0  = tid >> 2;               // 0..63 (rows r, r+64)

    const __half* gsrc[4];
    gsrc[0] = Ahi + (size_t)mb * K;
    gsrc[1] = Alo + (size_t)mb * K;
    gsrc[2] = Bhi + (size_t)nb * K;
    gsrc[3] = Blo + (size_t)nb * K;

    auto issue = [&](int buf, int k0) {
        const uint32_t st = sb0 + buf * STAGE_BYTES;
        #pragma unroll
        for (int sl = 0; sl < 4; sl++) {
            const __half* g = gsrc[sl] + k0;
            const uint32_t sd = st + sl * SLAB;
            cp16(sd + ld_r0 * ROWB + ld_col * 16,
                 g + (size_t)ld_r0 * K + ld_col * 8);
            cp16(sd + (ld_r0 + 64) * ROWB + ld_col * 16,
                 g + (size_t)(ld_r0 + 64) * K + ld_col * 8);
        }
    };

    const int nst = K >> 5;
    issue(0, 0);  cp_commit();
    issue(1, 32); cp_commit();

    int buf = 0;
    for (int s = 0; s < nst; s++) {
        cp_wait1();            // buf s%3 arrived
        __syncthreads();       // all warps done with buf (s-1)%3; data visible

        const int kn = (s + 2) << 5;
        if (kn < K) issue((s + 2) % 3, kn);
        cp_commit();

        const uint32_t st  = sb0 + buf * STAGE_BYTES;
        const uint32_t sAh = st;
        const uint32_t sAl = st + SLAB;
        const uint32_t sBh = st + 2 * SLAB;
        const uint32_t sBl = st + 3 * SLAB;

        #pragma unroll
        for (int kk = 0; kk < 2; kk++) {
            uint32_t ah[4][4], al[4][4], bh[2][4], bl[2][4];
            #pragma unroll
            for (int ma = 0; ma < 4; ma++)
                ldsm4(ah[ma], sAh + (uint32_t)(a_row + ma * 16) * ROWB
                              + kk * 32 + a_coff);
            #pragma unroll
            for (int n2 = 0; n2 < 2; n2++)
                ldsm4(bh[n2], sBh + (uint32_t)(b_row + n2 * 16) * ROWB
                              + kk * 32 + b_coff);
            #pragma unroll
            for (int n2 = 0; n2 < 2; n2++)
                ldsm4(bl[n2], sBl + (uint32_t)(b_row + n2 * 16) * ROWB
                              + kk * 32 + b_coff);
            // pass 1: Ahi * Bhi -> fp32 acc (half-rate pipe)
            #pragma unroll
            for (int ma = 0; ma < 4; ma++)
                #pragma unroll
                for (int na = 0; na < 4; na++)
                    mma16816(acc[ma][na], ah[ma], &bh[na >> 1][(na & 1) * 2]);
            // load Alo under MMA cover
            #pragma unroll
            for (int ma = 0; ma < 4; ma++)
                ldsm4(al[ma], sAl + (uint32_t)(a_row + ma * 16) * ROWB
                              + kk * 32 + a_coff);
            // pass 2: Ahi * Blo -> fp16 acc (full-rate)
            #pragma unroll
            for (int ma = 0; ma < 4; ma++)
                #pragma unroll
                for (int na = 0; na < 4; na++)
                    mma16816h(acch[ma][na], ah[ma], &bl[na >> 1][(na & 1) * 2]);
            // pass 3: Alo * Bhi -> fp16 acc (full-rate)
            #pragma unroll
            for (int ma = 0; ma < 4; ma++)
                #pragma unroll
                for (int na = 0; na < 4; na++)
                    mma16816h(acch[ma][na], al[ma], &bh[na >> 1][(na & 1) * 2]);
        }
        buf = (buf == 2) ? 0 : buf + 1;
    }

    // ---- epilogue: merge fp16 lo-acc into fp32, bias, activation ----
    const int g  = lane >> 2;
    const int tg = lane & 3;
    #pragma unroll
    for (int ma = 0; ma < 4; ma++) {
        #pragma unroll
        for (int na = 0; na < 4; na++) {
            const int m = mb + m_warp + ma * 16 + g;
            const int n = nb + n_warp + na * 8 + tg * 2;
            const float2 bv = *(const float2*)&bias[n];
            const __half2 h2a = *(__half2*)&acch[ma][na][0];
            const __half2 h2b = *(__half2*)&acch[ma][na][1];
            float y0 = acc[ma][na][0] + __low2float(h2a)  + bv.x;
            float y1 = acc[ma][na][1] + __high2float(h2a) + bv.y;
            float y2 = acc[ma][na][2] + __low2float(h2b)  + bv.x;
            float y3 = acc[ma][na][3] + __high2float(h2b) + bv.y;
            if (MODE == 0) {
                if (n >= 512 && n < 1536) {
                    y0 = 1.f / (1.f + __expf(-y0));
                    y1 = 1.f / (1.f + __expf(-y1));
                    y2 = 1.f / (1.f + __expf(-y2));
                    y3 = 1.f / (1.f + __expf(-y3));
                }
                *(float2*)&Yf[(size_t)m * ldy + n]       = make_float2(y0, y1);
                *(float2*)&Yf[(size_t)(m + 8) * ldy + n] = make_float2(y2, y3);
            } else {
                __half h0 = __float2half_rn(y0), h1 = __float2half_rn(y1);
                __half h2 = __float2half_rn(y2), h3 = __float2half_rn(y3);
                __half l0 = __float2half_rn(y0 - __half2float(h0));
                __half l1 = __float2half_rn(y1 - __half2float(h1));
                __half l2 = __float2half_rn(y2 - __half2float(h2));
                __half l3 = __float2half_rn(y3 - __half2float(h3));
                *(__half2*)&Yhi[(size_t)m * ldy + n]       = __halves2half2(h0, h1);
                *(__half2*)&Yhi[(size_t)(m + 8) * ldy + n] = __halves2half2(h2, h3);
                *(__half2*)&Ylo[(size_t)m * ldy + n]       = __halves2half2(l0, l1);
                *(__half2*)&Ylo[(size_t)(m + 8) * ldy + n] = __halves2half2(l2, l3);
            }
        }
    }
}

// ---------------------------------------------------------------------------
// Scan: one thread per (b,o). Y layout [M,2048] = x|f|r|cx (f/r sigmoided).
// Depth-4 software prefetch.
// ---------------------------------------------------------------------------
template <int SPLIT>
__global__ __launch_bounds__(128)
void sru_scan(const float* __restrict__ Y, const float* __restrict__ c0,
              float* __restrict__ hf,
              __half* __restrict__ hhi, __half* __restrict__ hlo,
              float* __restrict__ cout)
{
    const int e = blockIdx.x * 128 + threadIdx.x;
    const int b = e >> 9, o = e & 511;
    float c = c0[e];

    const float* p = Y + (size_t)b * NBIG + o;
    const size_t STEP = (size_t)BATCH * NBIG;

    float X[4], F[4], R[4], CX[4];
    #pragma unroll
    for (int i = 0; i < 4; i++) {
        const float* q = p + (size_t)i * STEP;
        X[i] = q[0]; F[i] = q[512]; R[i] = q[1024]; CX[i] = q[1536];
    }

    for (int t = 0; t < T_STEPS; t += 4) {
        #pragma unroll
        for (int j = 0; j < 4; j++) {
            const float x  = X[j];
            const float f  = F[j];
            const float r  = R[j];
            const float cx = CX[j];
            const int tp = t + 4 + j;
            if (tp < T_STEPS) {
                const float* q = p + (size_t)tp * STEP;
                X[j] = q[0]; F[j] = q[512]; R[j] = q[1024]; CX[j] = q[1536];
            }
            c = fmaf(f, c - x, x);
            const float h = fmaf(r, tanhf(c) - cx, cx);
            const size_t oi = (size_t)((t + j) * BATCH + b) * NOUT + o;
            if (SPLIT) {
                __half hh = __float2half_rn(h);
                hhi[oi] = hh;
                hlo[oi] = __float2half_rn(h - __half2float(hh));
            } else {
                hf[oi] = h;
            }
        }
    }
    if (!SPLIT) cout[e] = c;
}

// ---------------------------------------------------------------------------
__global__ __launch_bounds__(256)
void split_f32(const float4* __restrict__ src, uint2* __restrict__ hi,
               uint2* __restrict__ lo, int n4)
{
    const int i = blockIdx.x * 256 + threadIdx.x;
    if (i >= n4) return;
    float4 v = src[i];
    float a[4] = { v.x, v.y, v.z, v.w };
    __align__(8) __half h[4], l[4];
    #pragma unroll
    for (int j = 0; j < 4; j++) {
        h[j] = __float2half_rn(a[j]);
        l[j] = __float2half_rn(a[j] - __half2float(h[j]));
    }
    hi[i] = *(uint2*)h;
    lo[i] = *(uint2*)l;
}

__global__ __launch_bounds__(256)
void pack_w(const float* __restrict__ Wx, const float* __restrict__ Wf,
            const float* __restrict__ Wr, const float* __restrict__ Wcx,
            const float* __restrict__ bf, const float* __restrict__ br,
            const float* __restrict__ bcx)
{
    const int i = blockIdx.x * 256 + threadIdx.x;   // float4 idx, 524288 total
    const int n = i * 4;
    const int row = n >> 10, col = n & 1023;
    const int sel = row >> 9, lr = row & 511;
    const float* src = sel == 0 ? Wx : sel == 1 ? Wf : sel == 2 ? Wr : Wcx;
    float4 v = *(const float4*)(src + (size_t)lr * 1024 + col);
    float a[4] = { v.x, v.y, v.z, v.w };
    __align__(8) __half h[4], l[4];
    #pragma unroll
    for (int j = 0; j < 4; j++) {
        h[j] = __float2half_rn(a[j]);
        l[j] = __float2half_rn(a[j] - __half2float(h[j]));
    }
    ((uint2*)g_whi)[i] = *(uint2*)h;
    ((uint2*)g_wlo)[i] = *(uint2*)l;

    if (i < 512) {
        const int nb_ = i * 4;
        const int s2 = nb_ >> 9, off = nb_ & 511;
        float4 bv = make_float4(0.f, 0.f, 0.f, 0.f);
        if (s2 > 0) {
            const float* bs = s2 == 1 ? bf : s2 == 2 ? br : bcx;
            bv = *(const float4*)(bs + off);
        }
        *(float4*)(g_bias + nb_) = bv;
    }
}

__global__ __launch_bounds__(256)
void pack_wxl(const float* __restrict__ Wxl)
{
    const int i = blockIdx.x * 256 + threadIdx.x;   // 131072 float4s
    float4 v = *(const float4*)(Wxl + (size_t)i * 4);
    float a[4] = { v.x, v.y, v.z, v.w };
    __align__(8) __half h[4], l[4];
    #pragma unroll
    for (int j = 0; j < 4; j++) {
        h[j] = __float2half_rn(a[j]);
        l[j] = __float2half_rn(a[j] - __half2float(h[j]));
    }
    ((uint2*)g_wxlhi)[i] = *(uint2*)h;
    ((uint2*)g_wxllo)[i] = *(uint2*)l;
}

// ---------------------------------------------------------------------------
extern "C" void kernel_launch(void* const* d_in, const int* in_sizes, int n_in,
                              void* d_out, int out_size)
{
    (void)in_sizes; (void)n_in; (void)out_size;

    const float* xt   = (const float*)d_in[0];
    const float* ctf  = (const float*)d_in[1];
    const float* W_x  = (const float*)d_in[2];
    const float* W_f  = (const float*)d_in[3];
    const float* b_f  = (const float*)d_in[4];
    const float* W_r  = (const float*)d_in[5];
    const float* b_r  = (const float*)d_in[6];
    const float* W_cx = (const float*)d_in[7];
    const float* b_cx = (const float*)d_in[8];
    const float* W_xl = (const float*)d_in[9];
    const float* b_xl = (const float*)d_in[10];
    float* out = (float*)d_out;

    float *Y, *bias;
    __half *xhi, *xlo, *h1hi, *h1lo, *hchi, *hclo, *whi, *wlo, *wxlhi, *wxllo;
    cudaGetSymbolAddress((void**)&Y,     g_Y);
    cudaGetSymbolAddress((void**)&bias,  g_bias);
    cudaGetSymbolAddress((void**)&xhi,   g_xhi);
    cudaGetSymbolAddress((void**)&xlo,   g_xlo);
    cudaGetSymbolAddress((void**)&h1hi,  g_h1hi);
    cudaGetSymbolAddress((void**)&h1lo,  g_h1lo);
    cudaGetSymbolAddress((void**)&hchi,  g_hchi);
    cudaGetSymbolAddress((void**)&hclo,  g_hclo);
    cudaGetSymbolAddress((void**)&whi,   g_whi);
    cudaGetSymbolAddress((void**)&wlo,   g_wlo);
    cudaGetSymbolAddress((void**)&wxlhi, g_wxlhi);
    cudaGetSymbolAddress((void**)&wxllo, g_wxllo);

    cudaFuncSetAttribute(gemm_tc<0>, cudaFuncAttributeMaxDynamicSharedMemorySize,
                         GEMM_SMEM);
    cudaFuncSetAttribute(gemm_tc<1>, cudaFuncAttributeMaxDynamicSharedMemorySize,
                         GEMM_SMEM);

    pack_w<<<2048, 256>>>(W_x, W_f, W_r, W_cx, b_f, b_r, b_cx);
    pack_wxl<<<512, 256>>>(W_xl);
    split_f32<<<16384, 256>>>((const float4*)xt, (uint2*)xhi, (uint2*)xlo,
                              M_TOT * NIN / 4);

    // layer 0: fused 4-projection GEMM (N=2048) + scan
    gemm_tc<0><<<dim3(16, 128), 256, GEMM_SMEM>>>(xhi, xlo, whi, wlo, bias,
                                                  Y, nullptr, nullptr, NIN, NBIG);
    sru_scan<1><<<128, 128>>>(Y, ctf, nullptr, h1hi, h1lo, nullptr);

    // convert_x_layer: hconv = h1 @ W_xl^T + b_xl (fp16 hi/lo out)
    gemm_tc<1><<<dim3(8, 128), 256, GEMM_SMEM>>>(h1hi, h1lo, wxlhi, wxllo, b_xl,
                                                 nullptr, hchi, hclo, NOUT, NIN);

    // layer 1: fused 4-projection GEMM + scan
    gemm_tc<0><<<dim3(16, 128), 256, GEMM_SMEM>>>(hchi, hclo, whi, wlo, bias,
                                                  Y, nullptr, nullptr, NIN, NBIG);
    sru_scan<0><<<128, 128>>>(Y, ctf + E_TOT, out, nullptr, nullptr,
                              out + (size_t)M_TOT * NOUT);
}

// round 13
// speedup vs baseline: 1.1071x; 1.1071x over previous
#include <cuda_runtime.h>
#include <cuda_fp16.h>
#include <math.h>
#include <stdint.h>

// ---------------------------------------------------------------------------
// SRU, 2 layers. Legacy mma.sync HMMA (base sm_103 target; no tcgen05).
// Split-fp16 3-term GEMM: Y = Ahi*Bhi + Ahi*Blo + Alo*Bhi  (rel ~1e-5)
// R13: best-of composite — R10 GEMM (BK=32, 2-stage, 2 CTAs/SM; measured
//      561us) + R11 depth-4-prefetch scans. All fp32 accumulators.
// ---------------------------------------------------------------------------

#define T_STEPS 512
#define BATCH   32
#define NIN     1024
#define NOUT    512
#define M_TOT   16384
#define NBIG    2048
#define E_TOT   16384

__device__ __align__(256) float  g_Y[(size_t)M_TOT * NBIG];
__device__ __align__(256) __half g_xhi[(size_t)M_TOT * NIN];
__device__ __align__(256) __half g_xlo[(size_t)M_TOT * NIN];
__device__ __align__(256) __half g_h1hi[(size_t)M_TOT * NOUT];
__device__ __align__(256) __half g_h1lo[(size_t)M_TOT * NOUT];
__device__ __align__(256) __half g_hchi[(size_t)M_TOT * NIN];
__device__ __align__(256) __half g_hclo[(size_t)M_TOT * NIN];
__device__ __align__(256) __half g_whi[(size_t)NBIG * NIN];
__device__ __align__(256) __half g_wlo[(size_t)NBIG * NIN];
__device__ __align__(256) __half g_wxlhi[(size_t)NIN * NOUT];
__device__ __align__(256) __half g_wxllo[(size_t)NIN * NOUT];
__device__ __align__(256) float  g_bias[NBIG];

// ---------------------------------------------------------------------------
__device__ __forceinline__ uint32_t smem_u32(const void* p) {
    uint32_t a;
    asm("{ .reg .u64 t; cvta.to.shared.u64 t, %1; cvt.u32.u64 %0, t; }"
        : "=r"(a) : "l"(p));
    return a;
}
__device__ __forceinline__ void cp16(uint32_t d, const void* s) {
    asm volatile("cp.async.cg.shared.global [%0], [%1], 16;"
                 :: "r"(d), "l"(s) : "memory");
}
__device__ __forceinline__ void cp_commit() {
    asm volatile("cp.async.commit_group;" ::: "memory");
}
__device__ __forceinline__ void cp_wait1() {
    asm volatile("cp.async.wait_group 1;" ::: "memory");
}
__device__ __forceinline__ void ldsm4(uint32_t* r, uint32_t a) {
    asm volatile("ldmatrix.sync.aligned.m8n8.x4.shared.b16 {%0,%1,%2,%3}, [%4];"
                 : "=r"(r[0]), "=r"(r[1]), "=r"(r[2]), "=r"(r[3]) : "r"(a));
}
__device__ __forceinline__ void mma16816(float* c, const uint32_t* a,
                                         const uint32_t* b) {
    asm volatile(
        "mma.sync.aligned.m16n8k16.row.col.f32.f16.f16.f32 "
        "{%0,%1,%2,%3}, {%4,%5,%6,%7}, {%8,%9}, {%0,%1,%2,%3};"
        : "+f"(c[0]), "+f"(c[1]), "+f"(c[2]), "+f"(c[3])
        : "r"(a[0]), "r"(a[1]), "r"(a[2]), "r"(a[3]), "r"(b[0]), "r"(b[1]));
}

// ---------------------------------------------------------------------------
// GEMM: Y[M,N] = Ahi*Bhi^T + Ahi*Blo^T + Alo*Bhi^T   (all K-major)
// BM=128 BN=128 BK=32, 256 threads (8 warps: 2m x 4n, warp 64x32),
// 2-stage cp.async, 2 CTAs/SM. Smem rows 80B (conflict-free ldmatrix).
// MODE 0: fp32 out + g_bias + sigmoid on n in [512,1536)
// MODE 1: fp16 hi/lo out + fp32 bias vector
// ---------------------------------------------------------------------------
#define ROWB        80
#define SLAB        (128 * ROWB)            // 10240 B  (one 128x32-half tile)
#define STAGE_BYTES (4 * SLAB)              // 40960 B  (Ahi|Alo|Bhi|Blo)
#define GEMM_SMEM   (2 * STAGE_BYTES)       // 81920 B  -> 2 CTAs/SM

template <int MODE>
__global__ __launch_bounds__(256, 2)
void gemm_tc(const __half* __restrict__ Ahi, const __half* __restrict__ Alo,
             const __half* __restrict__ Bhi, const __half* __restrict__ Blo,
             const float* __restrict__ bias,
             float* __restrict__ Yf,
             __half* __restrict__ Yhi, __half* __restrict__ Ylo,
             int K, int ldy)
{
    extern __shared__ __align__(128) char smem_dyn[];
    const uint32_t sb0 = smem_u32(smem_dyn);

    const int tid  = threadIdx.x;
    const int lane = tid & 31;
    const int wid  = tid >> 5;               // 0..7
    const int m_warp = (wid >> 2) * 64;      // 0,64
    const int n_warp = (wid & 3) * 32;       // 0..96
    const int mb = blockIdx.y * 128;
    const int nb = blockIdx.x * 128;

    // ldmatrix lane addressing
    const int a_row  = m_warp + (lane & 15);
    const int a_coff = (lane >> 4) * 16;
    const int b_t    = lane >> 3;
    const int b_row  = n_warp + (b_t >> 1) * 8 + (lane & 7);
    const int b_coff = (b_t & 1) * 16;

    float acc[4][4][4];
    #pragma unroll
    for (int i = 0; i < 4; i++)
        #pragma unroll
        for (int j = 0; j < 4; j++)
            #pragma unroll
            for (int q = 0; q < 4; q++) acc[i][j][q] = 0.f;

    // cp.async mapping: per slab 512 16B chunks (128 rows x 4), 2 per thread.
    const int ld_col = tid & 3;               // 0..3 (x8 halves)
    const int ld_r0  = tid >> 2;              // 0..63 (rows r, r+64)

    const __half* gsrc[4];
    gsrc[0] = Ahi + (size_t)mb * K;
    gsrc[1] = Alo + (size_t)mb * K;
    gsrc[2] = Bhi + (size_t)nb * K;
    gsrc[3] = Blo + (size_t)nb * K;

    auto issue = [&](int buf, int k0) {
        const uint32_t st = sb0 + buf * STAGE_BYTES;
        #pragma unroll
        for (int sl = 0; sl < 4; sl++) {
            const __half* g = gsrc[sl] + k0;
            const uint32_t sd = st + sl * SLAB;
            cp16(sd + ld_r0 * ROWB + ld_col * 16,
                 g + (size_t)ld_r0 * K + ld_col * 8);
            cp16(sd + (ld_r0 + 64) * ROWB + ld_col * 16,
                 g + (size_t)(ld_r0 + 64) * K + ld_col * 8);
        }
    };

    const int nst = K >> 5;
    issue(0, 0);  cp_commit();
    issue(1, 32); cp_commit();

    for (int s = 0; s < nst; s++) {
        cp_wait1();            // stage s complete
        __syncthreads();       // visible to all warps

        const uint32_t st  = sb0 + (s & 1) * STAGE_BYTES;
        const uint32_t sAh = st;
        const uint32_t sAl = st + SLAB;
        const uint32_t sBh = st + 2 * SLAB;
        const uint32_t sBl = st + 3 * SLAB;

        #pragma unroll
        for (int kk = 0; kk < 2; kk++) {
            uint32_t ah[4][4], al[4][4], bh[2][4], bl[2][4];
            #pragma unroll
            for (int ma = 0; ma < 4; ma++)
                ldsm4(ah[ma], sAh + (uint32_t)(a_row + ma * 16) * ROWB
                              + kk * 32 + a_coff);
            #pragma unroll
            for (int n2 = 0; n2 < 2; n2++)
                ldsm4(bh[n2], sBh + (uint32_t)(b_row + n2 * 16) * ROWB
                              + kk * 32 + b_coff);
            #pragma unroll
            for (int n2 = 0; n2 < 2; n2++)
                ldsm4(bl[n2], sBl + (uint32_t)(b_row + n2 * 16) * ROWB
                              + kk * 32 + b_coff);
            // pass 1: Ahi * Bhi
            #pragma unroll
            for (int ma = 0; ma < 4; ma++)
                #pragma unroll
                for (int na = 0; na < 4; na++)
                    mma16816(acc[ma][na], ah[ma], &bh[na >> 1][(na & 1) * 2]);
            // load Alo under MMA cover
            #pragma unroll
            for (int ma = 0; ma < 4; ma++)
                ldsm4(al[ma], sAl + (uint32_t)(a_row + ma * 16) * ROWB
                              + kk * 32 + a_coff);
            // pass 2: Ahi * Blo
            #pragma unroll
            for (int ma = 0; ma < 4; ma++)
                #pragma unroll
                for (int na = 0; na < 4; na++)
                    mma16816(acc[ma][na], ah[ma], &bl[na >> 1][(na & 1) * 2]);
            // pass 3: Alo * Bhi
            #pragma unroll
            for (int ma = 0; ma < 4; ma++)
                #pragma unroll
                for (int na = 0; na < 4; na++)
                    mma16816(acc[ma][na], al[ma], &bh[na >> 1][(na & 1) * 2]);
        }

        __syncthreads();       // all warps done reading buf s&1
        const int k_next = (s + 2) * 32;
        if (k_next < K) issue(s & 1, k_next);
        cp_commit();
    }

    // ---- epilogue ----
    const int g  = lane >> 2;
    const int tg = lane & 3;
    #pragma unroll
    for (int ma = 0; ma < 4; ma++) {
        #pragma unroll
        for (int na = 0; na < 4; na++) {
            const int m = mb + m_warp + ma * 16 + g;
            const int n = nb + n_warp + na * 8 + tg * 2;
            const float2 bv = *(const float2*)&bias[n];
            float y0 = acc[ma][na][0] + bv.x;
            float y1 = acc[ma][na][1] + bv.y;
            float y2 = acc[ma][na][2] + bv.x;
            float y3 = acc[ma][na][3] + bv.y;
            if (MODE == 0) {
                if (n >= 512 && n < 1536) {
                    y0 = 1.f / (1.f + __expf(-y0));
                    y1 = 1.f / (1.f + __expf(-y1));
                    y2 = 1.f / (1.f + __expf(-y2));
                    y3 = 1.f / (1.f + __expf(-y3));
                }
                *(float2*)&Yf[(size_t)m * ldy + n]       = make_float2(y0, y1);
                *(float2*)&Yf[(size_t)(m + 8) * ldy + n] = make_float2(y2, y3);
            } else {
                __half h0 = __float2half_rn(y0), h1 = __float2half_rn(y1);
                __half h2 = __float2half_rn(y2), h3 = __float2half_rn(y3);
                __half l0 = __float2half_rn(y0 - __half2float(h0));
                __half l1 = __float2half_rn(y1 - __half2float(h1));
                __half l2 = __float2half_rn(y2 - __half2float(h2));
                __half l3 = __float2half_rn(y3 - __half2float(h3));
                *(__half2*)&Yhi[(size_t)m * ldy + n]       = __halves2half2(h0, h1);
                *(__half2*)&Yhi[(size_t)(m + 8) * ldy + n] = __halves2half2(h2, h3);
                *(__half2*)&Ylo[(size_t)m * ldy + n]       = __halves2half2(l0, l1);
                *(__half2*)&Ylo[(size_t)(m + 8) * ldy + n] = __halves2half2(l2, l3);
            }
        }
    }
}

// ---------------------------------------------------------------------------
// Scan: one thread per (b,o). Y layout [M,2048] = x|f|r|cx (f/r sigmoided).
// Depth-4 software prefetch: loads for t+4 issued while computing t.
// ---------------------------------------------------------------------------
template <int SPLIT>
__global__ __launch_bounds__(128)
void sru_scan(const float* __restrict__ Y, const float* __restrict__ c0,
              float* __restrict__ hf,
              __half* __restrict__ hhi, __half* __restrict__ hlo,
              float* __restrict__ cout)
{
    const int e = blockIdx.x * 128 + threadIdx.x;
    const int b = e >> 9, o = e & 511;
    float c = c0[e];

    const float* p = Y + (size_t)b * NBIG + o;
    const size_t STEP = (size_t)BATCH * NBIG;      // 65536 floats per t

    float X[4], F[4], R[4], CX[4];
    #pragma unroll
    for (int i = 0; i < 4; i++) {
        const float* q = p + (size_t)i * STEP;
        X[i] = q[0]; F[i] = q[512]; R[i] = q[1024]; CX[i] = q[1536];
    }

    for (int t = 0; t < T_STEPS; t += 4) {
        #pragma unroll
        for (int j = 0; j < 4; j++) {
            const float x  = X[j];
            const float f  = F[j];
            const float r  = R[j];
            const float cx = CX[j];
            const int tp = t + 4 + j;
            if (tp < T_STEPS) {      // prefetch t+4+j into slot j
                const float* q = p + (size_t)tp * STEP;
                X[j] = q[0]; F[j] = q[512]; R[j] = q[1024]; CX[j] = q[1536];
            }
            c = fmaf(f, c - x, x);
            const float h = fmaf(r, tanhf(c) - cx, cx);
            const size_t oi = (size_t)((t + j) * BATCH + b) * NOUT + o;
            if (SPLIT) {
                __half hh = __float2half_rn(h);
                hhi[oi] = hh;
                hlo[oi] = __float2half_rn(h - __half2float(hh));
            } else {
                hf[oi] = h;
            }
        }
    }
    if (!SPLIT) cout[e] = c;
}

// ---------------------------------------------------------------------------
__global__ __launch_bounds__(256)
void split_f32(const float4* __restrict__ src, uint2* __restrict__ hi,
               uint2* __restrict__ lo, int n4)
{
    const int i = blockIdx.x * 256 + threadIdx.x;
    if (i >= n4) return;
    float4 v = src[i];
    float a[4] = { v.x, v.y, v.z, v.w };
    __align__(8) __half h[4], l[4];
    #pragma unroll
    for (int j = 0; j < 4; j++) {
        h[j] = __float2half_rn(a[j]);
        l[j] = __float2half_rn(a[j] - __half2float(h[j]));
    }
    hi[i] = *(uint2*)h;
    lo[i] = *(uint2*)l;
}

__global__ __launch_bounds__(256)
void pack_w(const float* __restrict__ Wx, const float* __restrict__ Wf,
            const float* __restrict__ Wr, const float* __restrict__ Wcx,
            const float* __restrict__ bf, const float* __restrict__ br,
            const float* __restrict__ bcx)
{
    const int i = blockIdx.x * 256 + threadIdx.x;   // float4 idx, 524288 total
    const int n = i * 4;
    const int row = n >> 10, col = n & 1023;
    const int sel = row >> 9, lr = row & 511;
    const float* src = sel == 0 ? Wx : sel == 1 ? Wf : sel == 2 ? Wr : Wcx;
    float4 v = *(const float4*)(src + (size_t)lr * 1024 + col);
    float a[4] = { v.x, v.y, v.z, v.w };
    __align__(8) __half h[4], l[4];
    #pragma unroll
    for (int j = 0; j < 4; j++) {
        h[j] = __float2half_rn(a[j]);
        l[j] = __float2half_rn(a[j] - __half2float(h[j]));
    }
    ((uint2*)g_whi)[i] = *(uint2*)h;
    ((uint2*)g_wlo)[i] = *(uint2*)l;

    if (i < 512) {
        const int nb_ = i * 4;
        const int s2 = nb_ >> 9, off = nb_ & 511;
        float4 bv = make_float4(0.f, 0.f, 0.f, 0.f);
        if (s2 > 0) {
            const float* bs = s2 == 1 ? bf : s2 == 2 ? br : bcx;
            bv = *(const float4*)(bs + off);
        }
        *(float4*)(g_bias + nb_) = bv;
    }
}

__global__ __launch_bounds__(256)
void pack_wxl(const float* __restrict__ Wxl)
{
    const int i = blockIdx.x * 256 + threadIdx.x;   // 131072 float4s
    float4 v = *(const float4*)(Wxl + (size_t)i * 4);
    float a[4] = { v.x, v.y, v.z, v.w };
    __align__(8) __half h[4], l[4];
    #pragma unroll
    for (int j = 0; j < 4; j++) {
        h[j] = __float2half_rn(a[j]);
        l[j] = __float2half_rn(a[j] - __half2float(h[j]));
    }
    ((uint2*)g_wxlhi)[i] = *(uint2*)h;
    ((uint2*)g_wxllo)[i] = *(uint2*)l;
}

// ---------------------------------------------------------------------------
extern "C" void kernel_launch(void* const* d_in, const int* in_sizes, int n_in,
                              void* d_out, int out_size)
{
    (void)in_sizes; (void)n_in; (void)out_size;

    const float* xt   = (const float*)d_in[0];
    const float* ctf  = (const float*)d_in[1];
    const float* W_x  = (const float*)d_in[2];
    const float* W_f  = (const float*)d_in[3];
    const float* b_f  = (const float*)d_in[4];
    const float* W_r  = (const float*)d_in[5];
    const float* b_r  = (const float*)d_in[6];
    const float* W_cx = (const float*)d_in[7];
    const float* b_cx = (const float*)d_in[8];
    const float* W_xl = (const float*)d_in[9];
    const float* b_xl = (const float*)d_in[10];
    float* out = (float*)d_out;

    float *Y, *bias;
    __half *xhi, *xlo, *h1hi, *h1lo, *hchi, *hclo, *whi, *wlo, *wxlhi, *wxllo;
    cudaGetSymbolAddress((void**)&Y,     g_Y);
    cudaGetSymbolAddress((void**)&bias,  g_bias);
    cudaGetSymbolAddress((void**)&xhi,   g_xhi);
    cudaGetSymbolAddress((void**)&xlo,   g_xlo);
    cudaGetSymbolAddress((void**)&h1hi,  g_h1hi);
    cudaGetSymbolAddress((void**)&h1lo,  g_h1lo);
    cudaGetSymbolAddress((void**)&hchi,  g_hchi);
    cudaGetSymbolAddress((void**)&hclo,  g_hclo);
    cudaGetSymbolAddress((void**)&whi,   g_whi);
    cudaGetSymbolAddress((void**)&wlo,   g_wlo);
    cudaGetSymbolAddress((void**)&wxlhi, g_wxlhi);
    cudaGetSymbolAddress((void**)&wxllo, g_wxllo);

    cudaFuncSetAttribute(gemm_tc<0>, cudaFuncAttributeMaxDynamicSharedMemorySize,
                         GEMM_SMEM);
    cudaFuncSetAttribute(gemm_tc<1>, cudaFuncAttributeMaxDynamicSharedMemorySize,
                         GEMM_SMEM);

    pack_w<<<2048, 256>>>(W_x, W_f, W_r, W_cx, b_f, b_r, b_cx);
    pack_wxl<<<512, 256>>>(W_xl);
    split_f32<<<16384, 256>>>((const float4*)xt, (uint2*)xhi, (uint2*)xlo,
                              M_TOT * NIN / 4);

    // layer 0: fused 4-projection GEMM (N=2048) + scan
    gemm_tc<0><<<dim3(16, 128), 256, GEMM_SMEM>>>(xhi, xlo, whi, wlo, bias,
                                                  Y, nullptr, nullptr, NIN, NBIG);
    sru_scan<1><<<128, 128>>>(Y, ctf, nullptr, h1hi, h1lo, nullptr);

    // convert_x_layer: hconv = h1 @ W_xl^T + b_xl (fp16 hi/lo out)
    gemm_tc<1><<<dim3(8, 128), 256, GEMM_SMEM>>>(h1hi, h1lo, wxlhi, wxllo, b_xl,
                                                 nullptr, hchi, hclo, NOUT, NIN);

    // layer 1: fused 4-projection GEMM + scan
    gemm_tc<0><<<dim3(16, 128), 256, GEMM_SMEM>>>(hchi, hclo, whi, wlo, bias,
                                                  Y, nullptr, nullptr, NIN, NBIG);
    sru_scan<0><<<128, 128>>>(Y, ctf + E_TOT, out, nullptr, nullptr,
                              out + (size_t)M_TOT * NOUT);
}

// round 14
// speedup vs baseline: 1.4649x; 1.3231x over previous
#include <cuda_runtime.h>
#include <cuda_fp16.h>
#include <math.h>
#include <stdint.h>

// ---------------------------------------------------------------------------
// SRU, 2 layers. Legacy mma.sync HMMA. Split-fp16 3-term GEMMs.
// R14: algebraic fusion of convert layer into layer-1 weights:
//   (h1*Wxl^T + b_xl)*Wp^T + bp  ==  h1*(Wp*Wxl)^T + (Wp*b_xl + bp)
//   Wcomb = Wp*Wxl precomputed by a tiny split-fp16 GEMM; layer-1 GEMM K=512.
// ---------------------------------------------------------------------------

#define T_STEPS 512
#define BATCH   32
#define NIN     1024
#define NOUT    512
#define M_TOT   16384
#define NBIG    2048
#define E_TOT   16384

__device__ __align__(256) float  g_Y[(size_t)M_TOT * NBIG];
__device__ __align__(256) __half g_xhi[(size_t)M_TOT * NIN];
__device__ __align__(256) __half g_xlo[(size_t)M_TOT * NIN];
__device__ __align__(256) __half g_h1hi[(size_t)M_TOT * NOUT];
__device__ __align__(256) __half g_h1lo[(size_t)M_TOT * NOUT];
__device__ __align__(256) __half g_whi[(size_t)NBIG * NIN];     // Wp hi [2048,1024]
__device__ __align__(256) __half g_wlo[(size_t)NBIG * NIN];
__device__ __align__(256) __half g_wxlThi[(size_t)NOUT * NIN];  // Wxl^T hi [512,1024]
__device__ __align__(256) __half g_wxlTlo[(size_t)NOUT * NIN];
__device__ __align__(256) __half g_wchi[(size_t)NBIG * NOUT];   // Wcomb hi [2048,512]
__device__ __align__(256) __half g_wclo[(size_t)NBIG * NOUT];
__device__ __align__(256) float  g_bias[NBIG];                  // layer-0 bias
__device__ __align__(256) float  g_bias2[NBIG];                 // layer-1 bias_comb

// ---------------------------------------------------------------------------
__device__ __forceinline__ uint32_t smem_u32(const void* p) {
    uint32_t a;
    asm("{ .reg .u64 t; cvta.to.shared.u64 t, %1; cvt.u32.u64 %0, t; }"
        : "=r"(a) : "l"(p));
    return a;
}
__device__ __forceinline__ void cp16(uint32_t d, const void* s) {
    asm volatile("cp.async.cg.shared.global [%0], [%1], 16;"
                 :: "r"(d), "l"(s) : "memory");
}
__device__ __forceinline__ void cp_commit() {
    asm volatile("cp.async.commit_group;" ::: "memory");
}
__device__ __forceinline__ void cp_wait1() {
    asm volatile("cp.async.wait_group 1;" ::: "memory");
}
__device__ __forceinline__ void ldsm4(uint32_t* r, uint32_t a) {
    asm volatile("ldmatrix.sync.aligned.m8n8.x4.shared.b16 {%0,%1,%2,%3}, [%4];"
                 : "=r"(r[0]), "=r"(r[1]), "=r"(r[2]), "=r"(r[3]) : "r"(a));
}
__device__ __forceinline__ void mma16816(float* c, const uint32_t* a,
                                         const uint32_t* b) {
    asm volatile(
        "mma.sync.aligned.m16n8k16.row.col.f32.f16.f16.f32 "
        "{%0,%1,%2,%3}, {%4,%5,%6,%7}, {%8,%9}, {%0,%1,%2,%3};"
        : "+f"(c[0]), "+f"(c[1]), "+f"(c[2]), "+f"(c[3])
        : "r"(a[0]), "r"(a[1]), "r"(a[2]), "r"(a[3]), "r"(b[0]), "r"(b[1]));
}

// ---------------------------------------------------------------------------
// GEMM: Y[M,N] = Ahi*Bhi^T + Ahi*Blo^T + Alo*Bhi^T   (all K-major)
// BM=128 BN=128 BK=32, 256 threads (8 warps: 2m x 4n, warp 64x32),
// 2-stage cp.async, 2 CTAs/SM. Smem rows 80B (conflict-free ldmatrix).
// MODE 0: fp32 out + bias + sigmoid on n in [512,1536)
// MODE 1: fp16 hi/lo out + fp32 bias vector
// ---------------------------------------------------------------------------
#define ROWB        80
#define SLAB        (128 * ROWB)            // 10240 B
#define STAGE_BYTES (4 * SLAB)              // 40960 B (Ahi|Alo|Bhi|Blo)
#define GEMM_SMEM   (2 * STAGE_BYTES)       // 81920 B -> 2 CTAs/SM

template <int MODE>
__global__ __launch_bounds__(256, 2)
void gemm_tc(const __half* __restrict__ Ahi, const __half* __restrict__ Alo,
             const __half* __restrict__ Bhi, const __half* __restrict__ Blo,
             const float* __restrict__ bias,
             float* __restrict__ Yf,
             __half* __restrict__ Yhi, __half* __restrict__ Ylo,
             int K, int ldy)
{
    extern __shared__ __align__(128) char smem_dyn[];
    const uint32_t sb0 = smem_u32(smem_dyn);

    const int tid  = threadIdx.x;
    const int lane = tid & 31;
    const int wid  = tid >> 5;
    const int m_warp = (wid >> 2) * 64;
    const int n_warp = (wid & 3) * 32;
    const int mb = blockIdx.y * 128;
    const int nb = blockIdx.x * 128;

    const int a_row  = m_warp + (lane & 15);
    const int a_coff = (lane >> 4) * 16;
    const int b_t    = lane >> 3;
    const int b_row  = n_warp + (b_t >> 1) * 8 + (lane & 7);
    const int b_coff = (b_t & 1) * 16;

    float acc[4][4][4];
    #pragma unroll
    for (int i = 0; i < 4; i++)
        #pragma unroll
        for (int j = 0; j < 4; j++)
            #pragma unroll
            for (int q = 0; q < 4; q++) acc[i][j][q] = 0.f;

    const int ld_col = tid & 3;
    const int ld_r0  = tid >> 2;

    const __half* gsrc[4];
    gsrc[0] = Ahi + (size_t)mb * K;
    gsrc[1] = Alo + (size_t)mb * K;
    gsrc[2] = Bhi + (size_t)nb * K;
    gsrc[3] = Blo + (size_t)nb * K;

    auto issue = [&](int buf, int k0) {
        const uint32_t st = sb0 + buf * STAGE_BYTES;
        #pragma unroll
        for (int sl = 0; sl < 4; sl++) {
            const __half* g = gsrc[sl] + k0;
            const uint32_t sd = st + sl * SLAB;
            cp16(sd + ld_r0 * ROWB + ld_col * 16,
                 g + (size_t)ld_r0 * K + ld_col * 8);
            cp16(sd + (ld_r0 + 64) * ROWB + ld_col * 16,
                 g + (size_t)(ld_r0 + 64) * K + ld_col * 8);
        }
    };

    const int nst = K >> 5;
    issue(0, 0);  cp_commit();
    issue(1, 32); cp_commit();

    for (int s = 0; s < nst; s++) {
        cp_wait1();
        __syncthreads();

        const uint32_t st  = sb0 + (s & 1) * STAGE_BYTES;
        const uint32_t sAh = st;
        const uint32_t sAl = st + SLAB;
        const uint32_t sBh = st + 2 * SLAB;
        const uint32_t sBl = st + 3 * SLAB;

        #pragma unroll
        for (int kk = 0; kk < 2; kk++) {
            uint32_t ah[4][4], al[4][4], bh[2][4], bl[2][4];
            #pragma unroll
            for (int ma = 0; ma < 4; ma++)
                ldsm4(ah[ma], sAh + (uint32_t)(a_row + ma * 16) * ROWB
                              + kk * 32 + a_coff);
            #pragma unroll
            for (int n2 = 0; n2 < 2; n2++)
                ldsm4(bh[n2], sBh + (uint32_t)(b_row + n2 * 16) * ROWB
                              + kk * 32 + b_coff);
            #pragma unroll
            for (int n2 = 0; n2 < 2; n2++)
                ldsm4(bl[n2], sBl + (uint32_t)(b_row + n2 * 16) * ROWB
                              + kk * 32 + b_coff);
            #pragma unroll
            for (int ma = 0; ma < 4; ma++)
                #pragma unroll
                for (int na = 0; na < 4; na++)
                    mma16816(acc[ma][na], ah[ma], &bh[na >> 1][(na & 1) * 2]);
            #pragma unroll
            for (int ma = 0; ma < 4; ma++)
                ldsm4(al[ma], sAl + (uint32_t)(a_row + ma * 16) * ROWB
                              + kk * 32 + a_coff);
            #pragma unroll
            for (int ma = 0; ma < 4; ma++)
                #pragma unroll
                for (int na = 0; na < 4; na++)
                    mma16816(acc[ma][na], ah[ma], &bl[na >> 1][(na & 1) * 2]);
            #pragma unroll
            for (int ma = 0; ma < 4; ma++)
                #pragma unroll
                for (int na = 0; na < 4; na++)
                    mma16816(acc[ma][na], al[ma], &bh[na >> 1][(na & 1) * 2]);
        }

        __syncthreads();
        const int k_next = (s + 2) * 32;
        if (k_next < K) issue(s & 1, k_next);
        cp_commit();
    }

    // ---- epilogue ----
    const int g  = lane >> 2;
    const int tg = lane & 3;
    #pragma unroll
    for (int ma = 0; ma < 4; ma++) {
        #pragma unroll
        for (int na = 0; na < 4; na++) {
            const int m = mb + m_warp + ma * 16 + g;
            const int n = nb + n_warp + na * 8 + tg * 2;
            const float2 bv = *(const float2*)&bias[n];
            float y0 = acc[ma][na][0] + bv.x;
            float y1 = acc[ma][na][1] + bv.y;
            float y2 = acc[ma][na][2] + bv.x;
            float y3 = acc[ma][na][3] + bv.y;
            if (MODE == 0) {
                if (n >= 512 && n < 1536) {
                    y0 = 1.f / (1.f + __expf(-y0));
                    y1 = 1.f / (1.f + __expf(-y1));
                    y2 = 1.f / (1.f + __expf(-y2));
                    y3 = 1.f / (1.f + __expf(-y3));
                }
                *(float2*)&Yf[(size_t)m * ldy + n]       = make_float2(y0, y1);
                *(float2*)&Yf[(size_t)(m + 8) * ldy + n] = make_float2(y2, y3);
            } else {
                __half h0 = __float2half_rn(y0), h1 = __float2half_rn(y1);
                __half h2 = __float2half_rn(y2), h3 = __float2half_rn(y3);
                __half l0 = __float2half_rn(y0 - __half2float(h0));
                __half l1 = __float2half_rn(y1 - __half2float(h1));
                __half l2 = __float2half_rn(y2 - __half2float(h2));
                __half l3 = __float2half_rn(y3 - __half2float(h3));
                *(__half2*)&Yhi[(size_t)m * ldy + n]       = __halves2half2(h0, h1);
                *(__half2*)&Yhi[(size_t)(m + 8) * ldy + n] = __halves2half2(h2, h3);
                *(__half2*)&Ylo[(size_t)m * ldy + n]       = __halves2half2(l0, l1);
                *(__half2*)&Ylo[(size_t)(m + 8) * ldy + n] = __halves2half2(l2, l3);
            }
        }
    }
}

// ---------------------------------------------------------------------------
// Scan with depth-4 prefetch. SPLIT=1 -> h as fp16 hi/lo; 0 -> fp32 + c_last.
// ---------------------------------------------------------------------------
template <int SPLIT>
__global__ __launch_bounds__(128)
void sru_scan(const float* __restrict__ Y, const float* __restrict__ c0,
              float* __restrict__ hf,
              __half* __restrict__ hhi, __half* __restrict__ hlo,
              float* __restrict__ cout)
{
    const int e = blockIdx.x * 128 + threadIdx.x;
    const int b = e >> 9, o = e & 511;
    float c = c0[e];

    const float* p = Y + (size_t)b * NBIG + o;
    const size_t STEP = (size_t)BATCH * NBIG;

    float X[4], F[4], R[4], CX[4];
    #pragma unroll
    for (int i = 0; i < 4; i++) {
        const float* q = p + (size_t)i * STEP;
        X[i] = q[0]; F[i] = q[512]; R[i] = q[1024]; CX[i] = q[1536];
    }

    for (int t = 0; t < T_STEPS; t += 4) {
        #pragma unroll
        for (int j = 0; j < 4; j++) {
            const float x  = X[j];
            const float f  = F[j];
            const float r  = R[j];
            const float cx = CX[j];
            const int tp = t + 4 + j;
            if (tp < T_STEPS) {
                const float* q = p + (size_t)tp * STEP;
                X[j] = q[0]; F[j] = q[512]; R[j] = q[1024]; CX[j] = q[1536];
            }
            c = fmaf(f, c - x, x);
            const float h = fmaf(r, tanhf(c) - cx, cx);
            const size_t oi = (size_t)((t + j) * BATCH + b) * NOUT + o;
            if (SPLIT) {
                __half hh = __float2half_rn(h);
                hhi[oi] = hh;
                hlo[oi] = __float2half_rn(h - __half2float(hh));
            } else {
                hf[oi] = h;
            }
        }
    }
    if (!SPLIT) cout[e] = c;
}

// ---------------------------------------------------------------------------
__global__ __launch_bounds__(256)
void split_f32(const float4* __restrict__ src, uint2* __restrict__ hi,
               uint2* __restrict__ lo, int n4)
{
    const int i = blockIdx.x * 256 + threadIdx.x;
    if (i >= n4) return;
    float4 v = src[i];
    float a[4] = { v.x, v.y, v.z, v.w };
    __align__(8) __half h[4], l[4];
    #pragma unroll
    for (int j = 0; j < 4; j++) {
        h[j] = __float2half_rn(a[j]);
        l[j] = __float2half_rn(a[j] - __half2float(h[j]));
    }
    hi[i] = *(uint2*)h;
    lo[i] = *(uint2*)l;
}

// Pack 4 projection weights -> Wp hi/lo [2048,1024] + bias [2048]
__global__ __launch_bounds__(256)
void pack_w(const float* __restrict__ Wx, const float* __restrict__ Wf,
            const float* __restrict__ Wr, const float* __restrict__ Wcx,
            const float* __restrict__ bf, const float* __restrict__ br,
            const float* __restrict__ bcx)
{
    const int i = blockIdx.x * 256 + threadIdx.x;   // float4 idx, 524288 total
    const int n = i * 4;
    const int row = n >> 10, col = n & 1023;
    const int sel = row >> 9, lr = row & 511;
    const float* src = sel == 0 ? Wx : sel == 1 ? Wf : sel == 2 ? Wr : Wcx;
    float4 v = *(const float4*)(src + (size_t)lr * 1024 + col);
    float a[4] = { v.x, v.y, v.z, v.w };
    __align__(8) __half h[4], l[4];
    #pragma unroll
    for (int j = 0; j < 4; j++) {
        h[j] = __float2half_rn(a[j]);
        l[j] = __float2half_rn(a[j] - __half2float(h[j]));
    }
    ((uint2*)g_whi)[i] = *(uint2*)h;
    ((uint2*)g_wlo)[i] = *(uint2*)l;

    if (i < 512) {
        const int nb_ = i * 4;
        const int s2 = nb_ >> 9, off = nb_ & 511;
        float4 bv = make_float4(0.f, 0.f, 0.f, 0.f);
        if (s2 > 0) {
            const float* bs = s2 == 1 ? bf : s2 == 2 ? br : bcx;
            bv = *(const float4*)(bs + off);
        }
        *(float4*)(g_bias + nb_) = bv;
    }
}

// Transpose-pack Wxl [1024,512] -> Wxl^T hi/lo [512,1024] (K-major for B op)
__global__ __launch_bounds__(256)
void pack_wxl_t(const float* __restrict__ Wxl)
{
    __shared__ float tile[32][33];
    const int j0 = blockIdx.x * 32;   // output row block (0..511)
    const int k0 = blockIdx.y * 32;   // output col block (0..1023)
    const int tx = threadIdx.x & 31;
    const int ty = threadIdx.x >> 5;  // 0..7
    #pragma unroll
    for (int r = ty; r < 32; r += 8)
        tile[r][tx] = Wxl[(size_t)(k0 + r) * NOUT + j0 + tx];
    __syncthreads();
    #pragma unroll
    for (int r = ty; r < 32; r += 8) {
        const int j = j0 + r;
        const float v = tile[tx][r];
        const __half h = __float2half_rn(v);
        g_wxlThi[(size_t)j * NIN + k0 + tx] = h;
        g_wxlTlo[(size_t)j * NIN + k0 + tx] =
            __float2half_rn(v - __half2float(h));
    }
}

// bias_comb[i] = dot(Wp_row_i, b_xl) + g_bias[i]   (one warp per row)
__global__ __launch_bounds__(256)
void bias_comb_k(const float* __restrict__ Wx, const float* __restrict__ Wf,
                 const float* __restrict__ Wr, const float* __restrict__ Wcx,
                 const float* __restrict__ bxl)
{
    const int row  = blockIdx.x * 8 + (threadIdx.x >> 5);   // 0..2047
    const int lane = threadIdx.x & 31;
    const int sel = row >> 9, lr = row & 511;
    const float* src = sel == 0 ? Wx : sel == 1 ? Wf : sel == 2 ? Wr : Wcx;
    const float* w = src + (size_t)lr * NIN;
    float s = 0.f;
    #pragma unroll 4
    for (int k = lane; k < NIN; k += 32) s = fmaf(w[k], bxl[k], s);
    #pragma unroll
    for (int o = 16; o; o >>= 1) s += __shfl_xor_sync(0xFFFFFFFFu, s, o);
    if (lane == 0) g_bias2[row] = s + g_bias[row];
}

// ---------------------------------------------------------------------------
extern "C" void kernel_launch(void* const* d_in, const int* in_sizes, int n_in,
                              void* d_out, int out_size)
{
    (void)in_sizes; (void)n_in; (void)out_size;

    const float* xt   = (const float*)d_in[0];
    const float* ctf  = (const float*)d_in[1];
    const float* W_x  = (const float*)d_in[2];
    const float* W_f  = (const float*)d_in[3];
    const float* b_f  = (const float*)d_in[4];
    const float* W_r  = (const float*)d_in[5];
    const float* b_r  = (const float*)d_in[6];
    const float* W_cx = (const float*)d_in[7];
    const float* b_cx = (const float*)d_in[8];
    const float* W_xl = (const float*)d_in[9];
    const float* b_xl = (const float*)d_in[10];
    float* out = (float*)d_out;

    float *Y, *bias, *bias2;
    __half *xhi, *xlo, *h1hi, *h1lo, *whi, *wlo, *wxlThi, *wxlTlo, *wchi, *wclo;
    cudaGetSymbolAddress((void**)&Y,      g_Y);
    cudaGetSymbolAddress((void**)&bias,   g_bias);
    cudaGetSymbolAddress((void**)&bias2,  g_bias2);
    cudaGetSymbolAddress((void**)&xhi,    g_xhi);
    cudaGetSymbolAddress((void**)&xlo,    g_xlo);
    cudaGetSymbolAddress((void**)&h1hi,   g_h1hi);
    cudaGetSymbolAddress((void**)&h1lo,   g_h1lo);
    cudaGetSymbolAddress((void**)&whi,    g_whi);
    cudaGetSymbolAddress((void**)&wlo,    g_wlo);
    cudaGetSymbolAddress((void**)&wxlThi, g_wxlThi);
    cudaGetSymbolAddress((void**)&wxlTlo, g_wxlTlo);
    cudaGetSymbolAddress((void**)&wchi,   g_wchi);
    cudaGetSymbolAddress((void**)&wclo,   g_wclo);

    cudaFuncSetAttribute(gemm_tc<0>, cudaFuncAttributeMaxDynamicSharedMemorySize,
                         GEMM_SMEM);
    cudaFuncSetAttribute(gemm_tc<1>, cudaFuncAttributeMaxDynamicSharedMemorySize,
                         GEMM_SMEM);

    // ---- packing / precompute ----
    pack_w<<<2048, 256>>>(W_x, W_f, W_r, W_cx, b_f, b_r, b_cx);
    pack_wxl_t<<<dim3(16, 32), 256>>>(W_xl);
    split_f32<<<16384, 256>>>((const float4*)xt, (uint2*)xhi, (uint2*)xlo,
                              M_TOT * NIN / 4);
    bias_comb_k<<<256, 256>>>(W_x, W_f, W_r, W_cx, b_xl);

    // Wcomb[2048,512] = Wp[2048,1024] * Wxl^T[512,1024]^T  (hi/lo out, bias=0:
    // g_bias[0:512) is zero). grid (N/128, M/128) = (4, 16).
    gemm_tc<1><<<dim3(4, 16), 256, GEMM_SMEM>>>(whi, wlo, wxlThi, wxlTlo, bias,
                                                nullptr, wchi, wclo, NIN, NOUT);

    // ---- layer 0: fused 4-projection GEMM (K=1024) + scan ----
    gemm_tc<0><<<dim3(16, 128), 256, GEMM_SMEM>>>(xhi, xlo, whi, wlo, bias,
                                                  Y, nullptr, nullptr, NIN, NBIG);
    sru_scan<1><<<128, 128>>>(Y, ctf, nullptr, h1hi, h1lo, nullptr);

    // ---- layer 1: combined GEMM (K=512) + scan ----
    gemm_tc<0><<<dim3(16, 128), 256, GEMM_SMEM>>>(h1hi, h1lo, wchi, wclo, bias2,
                                                  Y, nullptr, nullptr, NOUT, NBIG);
    sru_scan<0><<<128, 128>>>(Y, ctf + E_TOT, out, nullptr, nullptr,
                              out + (size_t)M_TOT * NOUT);
}

// round 15
// speedup vs baseline: 1.5592x; 1.0644x over previous
#include <cuda_runtime.h>
#include <cuda_fp16.h>
#include <math.h>
#include <stdint.h>

// ---------------------------------------------------------------------------
// SRU, 2 layers. Legacy mma.sync HMMA. Split-fp16 3-term GEMMs.
// R15: chunked pipeline over T (4 chunks of 128) with capture-forked streams:
//   scans run on an aux stream overlapped with the next GEMM chunk; the
//   weight-combine branch (pack_w/pack_wxl_t/bias_comb/Wcomb) overlaps GEMM0.
//   (h1*Wxl^T+b_xl)*Wp^T+bp == h1*(Wp*Wxl)^T + (Wp*b_xl+bp)  [R14 fusion]
// ---------------------------------------------------------------------------

#define T_STEPS 512
#define BATCH   32
#define NIN     1024
#define NOUT    512
#define M_TOT   16384
#define NBIG    2048
#define E_TOT   16384
#define TCH     128                        // T-steps per pipeline chunk
#define MCH     (TCH * BATCH)              // 4096 M-rows per chunk

__device__ __align__(256) float  g_Y[(size_t)M_TOT * NBIG];
__device__ __align__(256) __half g_xhi[(size_t)M_TOT * NIN];
__device__ __align__(256) __half g_xlo[(size_t)M_TOT * NIN];
__device__ __align__(256) __half g_h1hi[(size_t)M_TOT * NOUT];
__device__ __align__(256) __half g_h1lo[(size_t)M_TOT * NOUT];
__device__ __align__(256) __half g_whi[(size_t)NBIG * NIN];     // Wp hi [2048,1024]
__device__ __align__(256) __half g_wlo[(size_t)NBIG * NIN];
__device__ __align__(256) __half g_wxlThi[(size_t)NOUT * NIN];  // Wxl^T hi [512,1024]
__device__ __align__(256) __half g_wxlTlo[(size_t)NOUT * NIN];
__device__ __align__(256) __half g_wchi[(size_t)NBIG * NOUT];   // Wcomb hi [2048,512]
__device__ __align__(256) __half g_wclo[(size_t)NBIG * NOUT];
__device__ __align__(256) float  g_bias[NBIG];
__device__ __align__(256) float  g_bias2[NBIG];
__device__ __align__(256) float  g_cst[E_TOT];                  // scan c carry

// ---------------------------------------------------------------------------
__device__ __forceinline__ uint32_t smem_u32(const void* p) {
    uint32_t a;
    asm("{ .reg .u64 t; cvta.to.shared.u64 t, %1; cvt.u32.u64 %0, t; }"
        : "=r"(a) : "l"(p));
    return a;
}
__device__ __forceinline__ void cp16(uint32_t d, const void* s) {
    asm volatile("cp.async.cg.shared.global [%0], [%1], 16;"
                 :: "r"(d), "l"(s) : "memory");
}
__device__ __forceinline__ void cp_commit() {
    asm volatile("cp.async.commit_group;" ::: "memory");
}
__device__ __forceinline__ void cp_wait1() {
    asm volatile("cp.async.wait_group 1;" ::: "memory");
}
__device__ __forceinline__ void ldsm4(uint32_t* r, uint32_t a) {
    asm volatile("ldmatrix.sync.aligned.m8n8.x4.shared.b16 {%0,%1,%2,%3}, [%4];"
                 : "=r"(r[0]), "=r"(r[1]), "=r"(r[2]), "=r"(r[3]) : "r"(a));
}
__device__ __forceinline__ void mma16816(float* c, const uint32_t* a,
                                         const uint32_t* b) {
    asm volatile(
        "mma.sync.aligned.m16n8k16.row.col.f32.f16.f16.f32 "
        "{%0,%1,%2,%3}, {%4,%5,%6,%7}, {%8,%9}, {%0,%1,%2,%3};"
        : "+f"(c[0]), "+f"(c[1]), "+f"(c[2]), "+f"(c[3])
        : "r"(a[0]), "r"(a[1]), "r"(a[2]), "r"(a[3]), "r"(b[0]), "r"(b[1]));
}

// ---------------------------------------------------------------------------
// GEMM: Y[M,N] = Ahi*Bhi^T + Ahi*Blo^T + Alo*Bhi^T   (all K-major)
// BM=128 BN=128 BK=32, 256 threads (8 warps: 2m x 4n, warp 64x32),
// 2-stage cp.async, 2 CTAs/SM.  m_off selects the M chunk.
// MODE 0: fp32 out + bias + sigmoid on n in [512,1536)
// MODE 1: fp16 hi/lo out + fp32 bias vector
// ---------------------------------------------------------------------------
#define ROWB        80
#define SLAB        (128 * ROWB)
#define STAGE_BYTES (4 * SLAB)
#define GEMM_SMEM   (2 * STAGE_BYTES)      // 81920 B -> 2 CTAs/SM

template <int MODE>
__global__ __launch_bounds__(256, 2)
void gemm_tc(const __half* __restrict__ Ahi, const __half* __restrict__ Alo,
             const __half* __restrict__ Bhi, const __half* __restrict__ Blo,
             const float* __restrict__ bias,
             float* __restrict__ Yf,
             __half* __restrict__ Yhi, __half* __restrict__ Ylo,
             int K, int ldy, int m_off)
{
    extern __shared__ __align__(128) char smem_dyn[];
    const uint32_t sb0 = smem_u32(smem_dyn);

    const int tid  = threadIdx.x;
    const int lane = tid & 31;
    const int wid  = tid >> 5;
    const int m_warp = (wid >> 2) * 64;
    const int n_warp = (wid & 3) * 32;
    const int mb = m_off + blockIdx.y * 128;
    const int nb = blockIdx.x * 128;

    const int a_row  = m_warp + (lane & 15);
    const int a_coff = (lane >> 4) * 16;
    const int b_t    = lane >> 3;
    const int b_row  = n_warp + (b_t >> 1) * 8 + (lane & 7);
    const int b_coff = (b_t & 1) * 16;

    float acc[4][4][4];
    #pragma unroll
    for (int i = 0; i < 4; i++)
        #pragma unroll
        for (int j = 0; j < 4; j++)
            #pragma unroll
            for (int q = 0; q < 4; q++) acc[i][j][q] = 0.f;

    const int ld_col = tid & 3;
    const int ld_r0  = tid >> 2;

    const __half* gsrc[4];
    gsrc[0] = Ahi + (size_t)mb * K;
    gsrc[1] = Alo + (size_t)mb * K;
    gsrc[2] = Bhi + (size_t)nb * K;
    gsrc[3] = Blo + (size_t)nb * K;

    auto issue = [&](int buf, int k0) {
        const uint32_t st = sb0 + buf * STAGE_BYTES;
        #pragma unroll
        for (int sl = 0; sl < 4; sl++) {
            const __half* g = gsrc[sl] + k0;
            const uint32_t sd = st + sl * SLAB;
            cp16(sd + ld_r0 * ROWB + ld_col * 16,
                 g + (size_t)ld_r0 * K + ld_col * 8);
            cp16(sd + (ld_r0 + 64) * ROWB + ld_col * 16,
                 g + (size_t)(ld_r0 + 64) * K + ld_col * 8);
        }
    };

    const int nst = K >> 5;
    issue(0, 0);  cp_commit();
    issue(1, 32); cp_commit();

    for (int s = 0; s < nst; s++) {
        cp_wait1();
        __syncthreads();

        const uint32_t st  = sb0 + (s & 1) * STAGE_BYTES;
        const uint32_t sAh = st;
        const uint32_t sAl = st + SLAB;
        const uint32_t sBh = st + 2 * SLAB;
        const uint32_t sBl = st + 3 * SLAB;

        #pragma unroll
        for (int kk = 0; kk < 2; kk++) {
            uint32_t ah[4][4], al[4][4], bh[2][4], bl[2][4];
            #pragma unroll
            for (int ma = 0; ma < 4; ma++)
                ldsm4(ah[ma], sAh + (uint32_t)(a_row + ma * 16) * ROWB
                              + kk * 32 + a_coff);
            #pragma unroll
            for (int n2 = 0; n2 < 2; n2++)
                ldsm4(bh[n2], sBh + (uint32_t)(b_row + n2 * 16) * ROWB
                              + kk * 32 + b_coff);
            #pragma unroll
            for (int n2 = 0; n2 < 2; n2++)
                ldsm4(bl[n2], sBl + (uint32_t)(b_row + n2 * 16) * ROWB
                              + kk * 32 + b_coff);
            #pragma unroll
            for (int ma = 0; ma < 4; ma++)
                #pragma unroll
                for (int na = 0; na < 4; na++)
                    mma16816(acc[ma][na], ah[ma], &bh[na >> 1][(na & 1) * 2]);
            #pragma unroll
            for (int ma = 0; ma < 4; ma++)
                ldsm4(al[ma], sAl + (uint32_t)(a_row + ma * 16) * ROWB
                              + kk * 32 + a_coff);
            #pragma unroll
            for (int ma = 0; ma < 4; ma++)
                #pragma unroll
                for (int na = 0; na < 4; na++)
                    mma16816(acc[ma][na], ah[ma], &bl[na >> 1][(na & 1) * 2]);
            #pragma unroll
            for (int ma = 0; ma < 4; ma++)
                #pragma unroll
                for (int na = 0; na < 4; na++)
                    mma16816(acc[ma][na], al[ma], &bh[na >> 1][(na & 1) * 2]);
        }

        __syncthreads();
        const int k_next = (s + 2) * 32;
        if (k_next < K) issue(s & 1, k_next);
        cp_commit();
    }

    // ---- epilogue ----
    const int g  = lane >> 2;
    const int tg = lane & 3;
    #pragma unroll
    for (int ma = 0; ma < 4; ma++) {
        #pragma unroll
        for (int na = 0; na < 4; na++) {
            const int m = mb + m_warp + ma * 16 + g;
            const int n = nb + n_warp + na * 8 + tg * 2;
            const float2 bv = *(const float2*)&bias[n];
            float y0 = acc[ma][na][0] + bv.x;
            float y1 = acc[ma][na][1] + bv.y;
            float y2 = acc[ma][na][2] + bv.x;
            float y3 = acc[ma][na][3] + bv.y;
            if (MODE == 0) {
                if (n >= 512 && n < 1536) {
                    y0 = 1.f / (1.f + __expf(-y0));
                    y1 = 1.f / (1.f + __expf(-y1));
                    y2 = 1.f / (1.f + __expf(-y2));
                    y3 = 1.f / (1.f + __expf(-y3));
                }
                *(float2*)&Yf[(size_t)m * ldy + n]       = make_float2(y0, y1);
                *(float2*)&Yf[(size_t)(m + 8) * ldy + n] = make_float2(y2, y3);
            } else {
                __half h0 = __float2half_rn(y0), h1 = __float2half_rn(y1);
                __half h2 = __float2half_rn(y2), h3 = __float2half_rn(y3);
                __half l0 = __float2half_rn(y0 - __half2float(h0));
                __half l1 = __float2half_rn(y1 - __half2float(h1));
                __half l2 = __float2half_rn(y2 - __half2float(h2));
                __half l3 = __float2half_rn(y3 - __half2float(h3));
                *(__half2*)&Yhi[(size_t)m * ldy + n]       = __halves2half2(h0, h1);
                *(__half2*)&Yhi[(size_t)(m + 8) * ldy + n] = __halves2half2(h2, h3);
                *(__half2*)&Ylo[(size_t)m * ldy + n]       = __halves2half2(l0, l1);
                *(__half2*)&Ylo[(size_t)(m + 8) * ldy + n] = __halves2half2(l2, l3);
            }
        }
    }
}

// ---------------------------------------------------------------------------
// Scan chunk: TCH steps starting at t0. Depth-4 prefetch. c carried via
// cin/cstate buffers. SPLIT=1 -> h as fp16 hi/lo; 0 -> fp32 h.
// ---------------------------------------------------------------------------
template <int SPLIT>
__global__ __launch_bounds__(128)
void sru_scan_chunk(const float* __restrict__ Y, const float* __restrict__ cin,
                    float* __restrict__ cstate, float* __restrict__ hf,
                    __half* __restrict__ hhi, __half* __restrict__ hlo, int t0)
{
    const int e = blockIdx.x * 128 + threadIdx.x;
    const int b = e >> 9, o = e & 511;
    float c = cin[e];

    const float* p = Y + (size_t)(t0 * BATCH + b) * NBIG + o;
    const size_t STEP = (size_t)BATCH * NBIG;

    float X[4], F[4], R[4], CX[4];
    #pragma unroll
    for (int i = 0; i < 4; i++) {
        const float* q = p + (size_t)i * STEP;
        X[i] = q[0]; F[i] = q[512]; R[i] = q[1024]; CX[i] = q[1536];
    }

    for (int t = 0; t < TCH; t += 4) {
        #pragma unroll
        for (int j = 0; j < 4; j++) {
            const float x  = X[j];
            const float f  = F[j];
            const float r  = R[j];
            const float cx = CX[j];
            const int tp = t + 4 + j;
            if (tp < TCH) {
                const float* q = p + (size_t)tp * STEP;
                X[j] = q[0]; F[j] = q[512]; R[j] = q[1024]; CX[j] = q[1536];
            }
            c = fmaf(f, c - x, x);
            const float h = fmaf(r, tanhf(c) - cx, cx);
            const size_t oi = (size_t)((t0 + t + j) * BATCH + b) * NOUT + o;
            if (SPLIT) {
                __half hh = __float2half_rn(h);
                hhi[oi] = hh;
                hlo[oi] = __float2half_rn(h - __half2float(hh));
            } else {
                hf[oi] = h;
            }
        }
    }
    cstate[e] = c;
}

// ---------------------------------------------------------------------------
__global__ __launch_bounds__(256)
void split_f32(const float4* __restrict__ src, uint2* __restrict__ hi,
               uint2* __restrict__ lo, int n4)
{
    const int i = blockIdx.x * 256 + threadIdx.x;
    if (i >= n4) return;
    float4 v = src[i];
    float a[4] = { v.x, v.y, v.z, v.w };
    __align__(8) __half h[4], l[4];
    #pragma unroll
    for (int j = 0; j < 4; j++) {
        h[j] = __float2half_rn(a[j]);
        l[j] = __float2half_rn(a[j] - __half2float(h[j]));
    }
    hi[i] = *(uint2*)h;
    lo[i] = *(uint2*)l;
}

__global__ __launch_bounds__(256)
void pack_w(const float* __restrict__ Wx, const float* __restrict__ Wf,
            const float* __restrict__ Wr, const float* __restrict__ Wcx,
            const float* __restrict__ bf, const float* __restrict__ br,
            const float* __restrict__ bcx)
{
    const int i = blockIdx.x * 256 + threadIdx.x;
    const int n = i * 4;
    const int row = n >> 10, col = n & 1023;
    const int sel = row >> 9, lr = row & 511;
    const float* src = sel == 0 ? Wx : sel == 1 ? Wf : sel == 2 ? Wr : Wcx;
    float4 v = *(const float4*)(src + (size_t)lr * 1024 + col);
    float a[4] = { v.x, v.y, v.z, v.w };
    __align__(8) __half h[4], l[4];
    #pragma unroll
    for (int j = 0; j < 4; j++) {
        h[j] = __float2half_rn(a[j]);
        l[j] = __float2half_rn(a[j] - __half2float(h[j]));
    }
    ((uint2*)g_whi)[i] = *(uint2*)h;
    ((uint2*)g_wlo)[i] = *(uint2*)l;

    if (i < 512) {
        const int nb_ = i * 4;
        const int s2 = nb_ >> 9, off = nb_ & 511;
        float4 bv = make_float4(0.f, 0.f, 0.f, 0.f);
        if (s2 > 0) {
            const float* bs = s2 == 1 ? bf : s2 == 2 ? br : bcx;
            bv = *(const float4*)(bs + off);
        }
        *(float4*)(g_bias + nb_) = bv;
    }
}

__global__ __launch_bounds__(256)
void pack_wxl_t(const float* __restrict__ Wxl)
{
    __shared__ float tile[32][33];
    const int j0 = blockIdx.x * 32;
    const int k0 = blockIdx.y * 32;
    const int tx = threadIdx.x & 31;
    const int ty = threadIdx.x >> 5;
    #pragma unroll
    for (int r = ty; r < 32; r += 8)
        tile[r][tx] = Wxl[(size_t)(k0 + r) * NOUT + j0 + tx];
    __syncthreads();
    #pragma unroll
    for (int r = ty; r < 32; r += 8) {
        const int j = j0 + r;
        const float v = tile[tx][r];
        const __half h = __float2half_rn(v);
        g_wxlThi[(size_t)j * NIN + k0 + tx] = h;
        g_wxlTlo[(size_t)j * NIN + k0 + tx] =
            __float2half_rn(v - __half2float(h));
    }
}

__global__ __launch_bounds__(256)
void bias_comb_k(const float* __restrict__ Wx, const float* __restrict__ Wf,
                 const float* __restrict__ Wr, const float* __restrict__ Wcx,
                 const float* __restrict__ bxl)
{
    const int row  = blockIdx.x * 8 + (threadIdx.x >> 5);
    const int lane = threadIdx.x & 31;
    const int sel = row >> 9, lr = row & 511;
    const float* src = sel == 0 ? Wx : sel == 1 ? Wf : sel == 2 ? Wr : Wcx;
    const float* w = src + (size_t)lr * NIN;
    float s = 0.f;
    #pragma unroll 4
    for (int k = lane; k < NIN; k += 32) s = fmaf(w[k], bxl[k], s);
    #pragma unroll
    for (int o = 16; o; o >>= 1) s += __shfl_xor_sync(0xFFFFFFFFu, s, o);
    if (lane == 0) g_bias2[row] = s + g_bias[row];
}

// ---------------------------------------------------------------------------
extern "C" void kernel_launch(void* const* d_in, const int* in_sizes, int n_in,
                              void* d_out, int out_size)
{
    (void)in_sizes; (void)n_in; (void)out_size;

    const float* xt   = (const float*)d_in[0];
    const float* ctf  = (const float*)d_in[1];
    const float* W_x  = (const float*)d_in[2];
    const float* W_f  = (const float*)d_in[3];
    const float* b_f  = (const float*)d_in[4];
    const float* W_r  = (const float*)d_in[5];
    const float* b_r  = (const float*)d_in[6];
    const float* W_cx = (const float*)d_in[7];
    const float* b_cx = (const float*)d_in[8];
    const float* W_xl = (const float*)d_in[9];
    const float* b_xl = (const float*)d_in[10];
    float* out = (float*)d_out;

    float *Y, *bias, *bias2, *cst;
    __half *xhi, *xlo, *h1hi, *h1lo, *whi, *wlo, *wxlThi, *wxlTlo, *wchi, *wclo;
    cudaGetSymbolAddress((void**)&Y,      g_Y);
    cudaGetSymbolAddress((void**)&bias,   g_bias);
    cudaGetSymbolAddress((void**)&bias2,  g_bias2);
    cudaGetSymbolAddress((void**)&cst,    g_cst);
    cudaGetSymbolAddress((void**)&xhi,    g_xhi);
    cudaGetSymbolAddress((void**)&xlo,    g_xlo);
    cudaGetSymbolAddress((void**)&h1hi,   g_h1hi);
    cudaGetSymbolAddress((void**)&h1lo,   g_h1lo);
    cudaGetSymbolAddress((void**)&whi,    g_whi);
    cudaGetSymbolAddress((void**)&wlo,    g_wlo);
    cudaGetSymbolAddress((void**)&wxlThi, g_wxlThi);
    cudaGetSymbolAddress((void**)&wxlTlo, g_wxlTlo);
    cudaGetSymbolAddress((void**)&wchi,   g_wchi);
    cudaGetSymbolAddress((void**)&wclo,   g_wclo);

    cudaFuncSetAttribute(gemm_tc<0>, cudaFuncAttributeMaxDynamicSharedMemorySize,
                         GEMM_SMEM);
    cudaFuncSetAttribute(gemm_tc<1>, cudaFuncAttributeMaxDynamicSharedMemorySize,
                         GEMM_SMEM);

    // one-time stream/event resources (created on first call, outside capture)
    static cudaStream_t aux = nullptr;
    static cudaEvent_t ev_root, ev_pw, ev_w, ev_end;
    static cudaEvent_t ev_g0[4], ev_s0[4], ev_g1[4];
    if (!aux) {
        cudaStreamCreateWithFlags(&aux, cudaStreamNonBlocking);
        cudaEventCreateWithFlags(&ev_root, cudaEventDisableTiming);
        cudaEventCreateWithFlags(&ev_pw,   cudaEventDisableTiming);
        cudaEventCreateWithFlags(&ev_w,    cudaEventDisableTiming);
        cudaEventCreateWithFlags(&ev_end,  cudaEventDisableTiming);
        for (int k = 0; k < 4; k++) {
            cudaEventCreateWithFlags(&ev_g0[k], cudaEventDisableTiming);
            cudaEventCreateWithFlags(&ev_s0[k], cudaEventDisableTiming);
            cudaEventCreateWithFlags(&ev_g1[k], cudaEventDisableTiming);
        }
    }

    // ---- fork aux off the main (capture) stream ----
    cudaEventRecord(ev_root, 0);
    cudaStreamWaitEvent(aux, ev_root, 0);

    // aux branch: weight packing + combined weights
    pack_w<<<2048, 256, 0, aux>>>(W_x, W_f, W_r, W_cx, b_f, b_r, b_cx);
    cudaEventRecord(ev_pw, aux);
    pack_wxl_t<<<dim3(16, 32), 256, 0, aux>>>(W_xl);
    bias_comb_k<<<256, 256, 0, aux>>>(W_x, W_f, W_r, W_cx, b_xl);
    gemm_tc<1><<<dim3(4, 16), 256, GEMM_SMEM, aux>>>(
        whi, wlo, wxlThi, wxlTlo, bias, nullptr, wchi, wclo, NIN, NOUT, 0);
    cudaEventRecord(ev_w, aux);

    // main stream: input split (concurrent with aux branch)
    split_f32<<<16384, 256>>>((const float4*)xt, (uint2*)xhi, (uint2*)xlo,
                              M_TOT * NIN / 4);
    cudaStreamWaitEvent(0, ev_pw, 0);   // GEMM0 needs whi/wlo + g_bias

    // ---- GEMM0 chunks (K=1024), scan0 chunks on aux ----
    for (int k = 0; k < 4; k++) {
        gemm_tc<0><<<dim3(16, 32), 256, GEMM_SMEM>>>(
            xhi, xlo, whi, wlo, bias, Y, nullptr, nullptr, NIN, NBIG, k * MCH);
        cudaEventRecord(ev_g0[k], 0);
    }
    for (int k = 0; k < 4; k++) {
        cudaStreamWaitEvent(aux, ev_g0[k], 0);
        sru_scan_chunk<1><<<128, 128, 0, aux>>>(
            Y, k == 0 ? ctf : cst, cst, nullptr, h1hi, h1lo, k * TCH);
        cudaEventRecord(ev_s0[k], aux);
    }

    // ---- GEMM1 chunks (K=512, combined weights), scan1 chunks on aux ----
    cudaStreamWaitEvent(0, ev_w, 0);    // needs wchi/wclo + bias2
    for (int k = 0; k < 4; k++) {
        cudaStreamWaitEvent(0, ev_s0[k], 0);   // h1 chunk k ready; Y chunk k free
        gemm_tc<0><<<dim3(16, 32), 256, GEMM_SMEM>>>(
            h1hi, h1lo, wchi, wclo, bias2, Y, nullptr, nullptr, NOUT, NBIG,
            k * MCH);
        cudaEventRecord(ev_g1[k], 0);
    }
    for (int k = 0; k < 4; k++) {
        cudaStreamWaitEvent(aux, ev_g1[k], 0);
        sru_scan_chunk<0><<<128, 128, 0, aux>>>(
            Y, k == 0 ? ctf + E_TOT : cst, 
            k == 3 ? out + (size_t)M_TOT * NOUT : cst,
            out, nullptr, nullptr, k * TCH);
    }

    // ---- join aux back into the main stream ----
    cudaEventRecord(ev_end, aux);
    cudaStreamWaitEvent(0, ev_end, 0);
}

// round 16
// speedup vs baseline: 1.6397x; 1.0516x over previous
#include <cuda_runtime.h>
#include <cuda_fp16.h>
#include <math.h>
#include <stdint.h>

// ---------------------------------------------------------------------------
// SRU, 2 layers. Legacy mma.sync HMMA. Split-fp16 3-term GEMMs.
// R16: 3-stream gap-filling pipeline.
//   - split_f32 chunked x4 on stream ss; GEMM0_k gated on split chunk k.
//   - GEMM1 chunks on stream gs gated on scan0_k -> fills GEMM0 tail waves.
//   - weight branch (pack_w/pack_wxl_t/bias_comb/Wcomb) on aux.
//   (h1*Wxl^T+b_xl)*Wp^T+bp == h1*(Wp*Wxl)^T + (Wp*b_xl+bp)  [R14 fusion]
// ---------------------------------------------------------------------------

#define T_STEPS 512
#define BATCH   32
#define NIN     1024
#define NOUT    512
#define M_TOT   16384
#define NBIG    2048
#define E_TOT   16384
#define TCH     128
#define MCH     (TCH * BATCH)              // 4096 M-rows per chunk

__device__ __align__(256) float  g_Y[(size_t)M_TOT * NBIG];
__device__ __align__(256) __half g_xhi[(size_t)M_TOT * NIN];
__device__ __align__(256) __half g_xlo[(size_t)M_TOT * NIN];
__device__ __align__(256) __half g_h1hi[(size_t)M_TOT * NOUT];
__device__ __align__(256) __half g_h1lo[(size_t)M_TOT * NOUT];
__device__ __align__(256) __half g_whi[(size_t)NBIG * NIN];
__device__ __align__(256) __half g_wlo[(size_t)NBIG * NIN];
__device__ __align__(256) __half g_wxlThi[(size_t)NOUT * NIN];
__device__ __align__(256) __half g_wxlTlo[(size_t)NOUT * NIN];
__device__ __align__(256) __half g_wchi[(size_t)NBIG * NOUT];
__device__ __align__(256) __half g_wclo[(size_t)NBIG * NOUT];
__device__ __align__(256) float  g_bias[NBIG];
__device__ __align__(256) float  g_bias2[NBIG];
__device__ __align__(256) float  g_cst[E_TOT];

// ---------------------------------------------------------------------------
__device__ __forceinline__ uint32_t smem_u32(const void* p) {
    uint32_t a;
    asm("{ .reg .u64 t; cvta.to.shared.u64 t, %1; cvt.u32.u64 %0, t; }"
        : "=r"(a) : "l"(p));
    return a;
}
__device__ __forceinline__ void cp16(uint32_t d, const void* s) {
    asm volatile("cp.async.cg.shared.global [%0], [%1], 16;"
                 :: "r"(d), "l"(s) : "memory");
}
__device__ __forceinline__ void cp_commit() {
    asm volatile("cp.async.commit_group;" ::: "memory");
}
__device__ __forceinline__ void cp_wait1() {
    asm volatile("cp.async.wait_group 1;" ::: "memory");
}
__device__ __forceinline__ void ldsm4(uint32_t* r, uint32_t a) {
    asm volatile("ldmatrix.sync.aligned.m8n8.x4.shared.b16 {%0,%1,%2,%3}, [%4];"
                 : "=r"(r[0]), "=r"(r[1]), "=r"(r[2]), "=r"(r[3]) : "r"(a));
}
__device__ __forceinline__ void mma16816(float* c, const uint32_t* a,
                                         const uint32_t* b) {
    asm volatile(
        "mma.sync.aligned.m16n8k16.row.col.f32.f16.f16.f32 "
        "{%0,%1,%2,%3}, {%4,%5,%6,%7}, {%8,%9}, {%0,%1,%2,%3};"
        : "+f"(c[0]), "+f"(c[1]), "+f"(c[2]), "+f"(c[3])
        : "r"(a[0]), "r"(a[1]), "r"(a[2]), "r"(a[3]), "r"(b[0]), "r"(b[1]));
}

// ---------------------------------------------------------------------------
#define ROWB        80
#define SLAB        (128 * ROWB)
#define STAGE_BYTES (4 * SLAB)
#define GEMM_SMEM   (2 * STAGE_BYTES)      // 81920 B -> 2 CTAs/SM

template <int MODE>
__global__ __launch_bounds__(256, 2)
void gemm_tc(const __half* __restrict__ Ahi, const __half* __restrict__ Alo,
             const __half* __restrict__ Bhi, const __half* __restrict__ Blo,
             const float* __restrict__ bias,
             float* __restrict__ Yf,
             __half* __restrict__ Yhi, __half* __restrict__ Ylo,
             int K, int ldy, int m_off)
{
    extern __shared__ __align__(128) char smem_dyn[];
    const uint32_t sb0 = smem_u32(smem_dyn);

    const int tid  = threadIdx.x;
    const int lane = tid & 31;
    const int wid  = tid >> 5;
    const int m_warp = (wid >> 2) * 64;
    const int n_warp = (wid & 3) * 32;
    const int mb = m_off + blockIdx.y * 128;
    const int nb = blockIdx.x * 128;

    const int a_row  = m_warp + (lane & 15);
    const int a_coff = (lane >> 4) * 16;
    const int b_t    = lane >> 3;
    const int b_row  = n_warp + (b_t >> 1) * 8 + (lane & 7);
    const int b_coff = (b_t & 1) * 16;

    float acc[4][4][4];
    #pragma unroll
    for (int i = 0; i < 4; i++)
        #pragma unroll
        for (int j = 0; j < 4; j++)
            #pragma unroll
            for (int q = 0; q < 4; q++) acc[i][j][q] = 0.f;

    const int ld_col = tid & 3;
    const int ld_r0  = tid >> 2;

    const __half* gsrc[4];
    gsrc[0] = Ahi + (size_t)mb * K;
    gsrc[1] = Alo + (size_t)mb * K;
    gsrc[2] = Bhi + (size_t)nb * K;
    gsrc[3] = Blo + (size_t)nb * K;

    auto issue = [&](int buf, int k0) {
        const uint32_t st = sb0 + buf * STAGE_BYTES;
        #pragma unroll
        for (int sl = 0; sl < 4; sl++) {
            const __half* g = gsrc[sl] + k0;
            const uint32_t sd = st + sl * SLAB;
            cp16(sd + ld_r0 * ROWB + ld_col * 16,
                 g + (size_t)ld_r0 * K + ld_col * 8);
            cp16(sd + (ld_r0 + 64) * ROWB + ld_col * 16,
                 g + (size_t)(ld_r0 + 64) * K + ld_col * 8);
        }
    };

    const int nst = K >> 5;
    issue(0, 0);  cp_commit();
    issue(1, 32); cp_commit();

    for (int s = 0; s < nst; s++) {
        cp_wait1();
        __syncthreads();

        const uint32_t st  = sb0 + (s & 1) * STAGE_BYTES;
        const uint32_t sAh = st;
        const uint32_t sAl = st + SLAB;
        const uint32_t sBh = st + 2 * SLAB;
        const uint32_t sBl = st + 3 * SLAB;

        #pragma unroll
        for (int kk = 0; kk < 2; kk++) {
            uint32_t ah[4][4], al[4][4], bh[2][4], bl[2][4];
            #pragma unroll
            for (int ma = 0; ma < 4; ma++)
                ldsm4(ah[ma], sAh + (uint32_t)(a_row + ma * 16) * ROWB
                              + kk * 32 + a_coff);
            #pragma unroll
            for (int n2 = 0; n2 < 2; n2++)
                ldsm4(bh[n2], sBh + (uint32_t)(b_row + n2 * 16) * ROWB
                              + kk * 32 + b_coff);
            #pragma unroll
            for (int n2 = 0; n2 < 2; n2++)
                ldsm4(bl[n2], sBl + (uint32_t)(b_row + n2 * 16) * ROWB
                              + kk * 32 + b_coff);
            #pragma unroll
            for (int ma = 0; ma < 4; ma++)
                #pragma unroll
                for (int na = 0; na < 4; na++)
                    mma16816(acc[ma][na], ah[ma], &bh[na >> 1][(na & 1) * 2]);
            #pragma unroll
            for (int ma = 0; ma < 4; ma++)
                ldsm4(al[ma], sAl + (uint32_t)(a_row + ma * 16) * ROWB
                              + kk * 32 + a_coff);
            #pragma unroll
            for (int ma = 0; ma < 4; ma++)
                #pragma unroll
                for (int na = 0; na < 4; na++)
                    mma16816(acc[ma][na], ah[ma], &bl[na >> 1][(na & 1) * 2]);
            #pragma unroll
            for (int ma = 0; ma < 4; ma++)
                #pragma unroll
                for (int na = 0; na < 4; na++)
                    mma16816(acc[ma][na], al[ma], &bh[na >> 1][(na & 1) * 2]);
        }

        __syncthreads();
        const int k_next = (s + 2) * 32;
        if (k_next < K) issue(s & 1, k_next);
        cp_commit();
    }

    // ---- epilogue ----
    const int g  = lane >> 2;
    const int tg = lane & 3;
    #pragma unroll
    for (int ma = 0; ma < 4; ma++) {
        #pragma unroll
        for (int na = 0; na < 4; na++) {
            const int m = mb + m_warp + ma * 16 + g;
            const int n = nb + n_warp + na * 8 + tg * 2;
            const float2 bv = *(const float2*)&bias[n];
            float y0 = acc[ma][na][0] + bv.x;
            float y1 = acc[ma][na][1] + bv.y;
            float y2 = acc[ma][na][2] + bv.x;
            float y3 = acc[ma][na][3] + bv.y;
            if (MODE == 0) {
                if (n >= 512 && n < 1536) {
                    y0 = 1.f / (1.f + __expf(-y0));
                    y1 = 1.f / (1.f + __expf(-y1));
                    y2 = 1.f / (1.f + __expf(-y2));
                    y3 = 1.f / (1.f + __expf(-y3));
                }
                *(float2*)&Yf[(size_t)m * ldy + n]       = make_float2(y0, y1);
                *(float2*)&Yf[(size_t)(m + 8) * ldy + n] = make_float2(y2, y3);
            } else {
                __half h0 = __float2half_rn(y0), h1 = __float2half_rn(y1);
                __half h2 = __float2half_rn(y2), h3 = __float2half_rn(y3);
                __half l0 = __float2half_rn(y0 - __half2float(h0));
                __half l1 = __float2half_rn(y1 - __half2float(h1));
                __half l2 = __float2half_rn(y2 - __half2float(h2));
                __half l3 = __float2half_rn(y3 - __half2float(h3));
                *(__half2*)&Yhi[(size_t)m * ldy + n]       = __halves2half2(h0, h1);
                *(__half2*)&Yhi[(size_t)(m + 8) * ldy + n] = __halves2half2(h2, h3);
                *(__half2*)&Ylo[(size_t)m * ldy + n]       = __halves2half2(l0, l1);
                *(__half2*)&Ylo[(size_t)(m + 8) * ldy + n] = __halves2half2(l2, l3);
            }
        }
    }
}

// ---------------------------------------------------------------------------
template <int SPLIT>
__global__ __launch_bounds__(128)
void sru_scan_chunk(const float* __restrict__ Y, const float* __restrict__ cin,
                    float* __restrict__ cstate, float* __restrict__ hf,
                    __half* __restrict__ hhi, __half* __restrict__ hlo, int t0)
{
    const int e = blockIdx.x * 128 + threadIdx.x;
    const int b = e >> 9, o = e & 511;
    float c = cin[e];

    const float* p = Y + (size_t)(t0 * BATCH + b) * NBIG + o;
    const size_t STEP = (size_t)BATCH * NBIG;

    float X[4], F[4], R[4], CX[4];
    #pragma unroll
    for (int i = 0; i < 4; i++) {
        const float* q = p + (size_t)i * STEP;
        X[i] = q[0]; F[i] = q[512]; R[i] = q[1024]; CX[i] = q[1536];
    }

    for (int t = 0; t < TCH; t += 4) {
        #pragma unroll
        for (int j = 0; j < 4; j++) {
            const float x  = X[j];
            const float f  = F[j];
            const float r  = R[j];
            const float cx = CX[j];
            const int tp = t + 4 + j;
            if (tp < TCH) {
                const float* q = p + (size_t)tp * STEP;
                X[j] = q[0]; F[j] = q[512]; R[j] = q[1024]; CX[j] = q[1536];
            }
            c = fmaf(f, c - x, x);
            const float h = fmaf(r, tanhf(c) - cx, cx);
            const size_t oi = (size_t)((t0 + t + j) * BATCH + b) * NOUT + o;
            if (SPLIT) {
                __half hh = __float2half_rn(h);
                hhi[oi] = hh;
                hlo[oi] = __float2half_rn(h - __half2float(hh));
            } else {
                hf[oi] = h;
            }
        }
    }
    cstate[e] = c;
}

// ---------------------------------------------------------------------------
__global__ __launch_bounds__(256)
void split_f32(const float4* __restrict__ src, uint2* __restrict__ hi,
               uint2* __restrict__ lo, int n4)
{
    const int i = blockIdx.x * 256 + threadIdx.x;
    if (i >= n4) return;
    float4 v = src[i];
    float a[4] = { v.x, v.y, v.z, v.w };
    __align__(8) __half h[4], l[4];
    #pragma unroll
    for (int j = 0; j < 4; j++) {
        h[j] = __float2half_rn(a[j]);
        l[j] = __float2half_rn(a[j] - __half2float(h[j]));
    }
    hi[i] = *(uint2*)h;
    lo[i] = *(uint2*)l;
}

__global__ __launch_bounds__(256)
void pack_w(const float* __restrict__ Wx, const float* __restrict__ Wf,
            const float* __restrict__ Wr, const float* __restrict__ Wcx,
            const float* __restrict__ bf, const float* __restrict__ br,
            const float* __restrict__ bcx)
{
    const int i = blockIdx.x * 256 + threadIdx.x;
    const int n = i * 4;
    const int row = n >> 10, col = n & 1023;
    const int sel = row >> 9, lr = row & 511;
    const float* src = sel == 0 ? Wx : sel == 1 ? Wf : sel == 2 ? Wr : Wcx;
    float4 v = *(const float4*)(src + (size_t)lr * 1024 + col);
    float a[4] = { v.x, v.y, v.z, v.w };
    __align__(8) __half h[4], l[4];
    #pragma unroll
    for (int j = 0; j < 4; j++) {
        h[j] = __float2half_rn(a[j]);
        l[j] = __float2half_rn(a[j] - __half2float(h[j]));
    }
    ((uint2*)g_whi)[i] = *(uint2*)h;
    ((uint2*)g_wlo)[i] = *(uint2*)l;

    if (i < 512) {
        const int nb_ = i * 4;
        const int s2 = nb_ >> 9, off = nb_ & 511;
        float4 bv = make_float4(0.f, 0.f, 0.f, 0.f);
        if (s2 > 0) {
            const float* bs = s2 == 1 ? bf : s2 == 2 ? br : bcx;
            bv = *(const float4*)(bs + off);
        }
        *(float4*)(g_bias + nb_) = bv;
    }
}

__global__ __launch_bounds__(256)
void pack_wxl_t(const float* __restrict__ Wxl)
{
    __shared__ float tile[32][33];
    const int j0 = blockIdx.x * 32;
    const int k0 = blockIdx.y * 32;
    const int tx = threadIdx.x & 31;
    const int ty = threadIdx.x >> 5;
    #pragma unroll
    for (int r = ty; r < 32; r += 8)
        tile[r][tx] = Wxl[(size_t)(k0 + r) * NOUT + j0 + tx];
    __syncthreads();
    #pragma unroll
    for (int r = ty; r < 32; r += 8) {
        const int j = j0 + r;
        const float v = tile[tx][r];
        const __half h = __float2half_rn(v);
        g_wxlThi[(size_t)j * NIN + k0 + tx] = h;
        g_wxlTlo[(size_t)j * NIN + k0 + tx] =
            __float2half_rn(v - __half2float(h));
    }
}

__global__ __launch_bounds__(256)
void bias_comb_k(const float* __restrict__ Wx, const float* __restrict__ Wf,
                 const float* __restrict__ Wr, const float* __restrict__ Wcx,
                 const float* __restrict__ bxl)
{
    const int row  = blockIdx.x * 8 + (threadIdx.x >> 5);
    const int lane = threadIdx.x & 31;
    const int sel = row >> 9, lr = row & 511;
    const float* src = sel == 0 ? Wx : sel == 1 ? Wf : sel == 2 ? Wr : Wcx;
    const float* w = src + (size_t)lr * NIN;
    float s = 0.f;
    #pragma unroll 4
    for (int k = lane; k < NIN; k += 32) s = fmaf(w[k], bxl[k], s);
    #pragma unroll
    for (int o = 16; o; o >>= 1) s += __shfl_xor_sync(0xFFFFFFFFu, s, o);
    if (lane == 0) g_bias2[row] = s + g_bias[row];
}

// ---------------------------------------------------------------------------
extern "C" void kernel_launch(void* const* d_in, const int* in_sizes, int n_in,
                              void* d_out, int out_size)
{
    (void)in_sizes; (void)n_in; (void)out_size;

    const float* xt   = (const float*)d_in[0];
    const float* ctf  = (const float*)d_in[1];
    const float* W_x  = (const float*)d_in[2];
    const float* W_f  = (const float*)d_in[3];
    const float* b_f  = (const float*)d_in[4];
    const float* W_r  = (const float*)d_in[5];
    const float* b_r  = (const float*)d_in[6];
    const float* W_cx = (const float*)d_in[7];
    const float* b_cx = (const float*)d_in[8];
    const float* W_xl = (const float*)d_in[9];
    const float* b_xl = (const float*)d_in[10];
    float* out = (float*)d_out;

    float *Y, *bias, *bias2, *cst;
    __half *xhi, *xlo, *h1hi, *h1lo, *whi, *wlo, *wxlThi, *wxlTlo, *wchi, *wclo;
    cudaGetSymbolAddress((void**)&Y,      g_Y);
    cudaGetSymbolAddress((void**)&bias,   g_bias);
    cudaGetSymbolAddress((void**)&bias2,  g_bias2);
    cudaGetSymbolAddress((void**)&cst,    g_cst);
    cudaGetSymbolAddress((void**)&xhi,    g_xhi);
    cudaGetSymbolAddress((void**)&xlo,    g_xlo);
    cudaGetSymbolAddress((void**)&h1hi,   g_h1hi);
    cudaGetSymbolAddress((void**)&h1lo,   g_h1lo);
    cudaGetSymbolAddress((void**)&whi,    g_whi);
    cudaGetSymbolAddress((void**)&wlo,    g_wlo);
    cudaGetSymbolAddress((void**)&wxlThi, g_wxlThi);
    cudaGetSymbolAddress((void**)&wxlTlo, g_wxlTlo);
    cudaGetSymbolAddress((void**)&wchi,   g_wchi);
    cudaGetSymbolAddress((void**)&wclo,   g_wclo);

    cudaFuncSetAttribute(gemm_tc<0>, cudaFuncAttributeMaxDynamicSharedMemorySize,
                         GEMM_SMEM);
    cudaFuncSetAttribute(gemm_tc<1>, cudaFuncAttributeMaxDynamicSharedMemorySize,
                         GEMM_SMEM);

    // one-time stream/event resources (created outside capture on first call)
    static cudaStream_t aux = nullptr, ss = nullptr, gs = nullptr;
    static cudaEvent_t ev_root, ev_pw, ev_w, ev_end;
    static cudaEvent_t ev_sp[4], ev_g0[4], ev_s0[4], ev_g1[4];
    if (!aux) {
        cudaStreamCreateWithFlags(&aux, cudaStreamNonBlocking);
        cudaStreamCreateWithFlags(&ss,  cudaStreamNonBlocking);
        cudaStreamCreateWithFlags(&gs,  cudaStreamNonBlocking);
        cudaEventCreateWithFlags(&ev_root, cudaEventDisableTiming);
        cudaEventCreateWithFlags(&ev_pw,   cudaEventDisableTiming);
        cudaEventCreateWithFlags(&ev_w,    cudaEventDisableTiming);
        cudaEventCreateWithFlags(&ev_end,  cudaEventDisableTiming);
        for (int k = 0; k < 4; k++) {
            cudaEventCreateWithFlags(&ev_sp[k], cudaEventDisableTiming);
            cudaEventCreateWithFlags(&ev_g0[k], cudaEventDisableTiming);
            cudaEventCreateWithFlags(&ev_s0[k], cudaEventDisableTiming);
            cudaEventCreateWithFlags(&ev_g1[k], cudaEventDisableTiming);
        }
    }

    // ---- fork side streams off the main (capture) stream ----
    cudaEventRecord(ev_root, 0);
    cudaStreamWaitEvent(aux, ev_root, 0);
    cudaStreamWaitEvent(ss,  ev_root, 0);
    cudaStreamWaitEvent(gs,  ev_root, 0);

    // ss: input split, chunked x4 (chunk k = M rows [k*MCH, (k+1)*MCH))
    const int SPC = MCH * NIN / 4;        // float4 per chunk (1M)
    for (int k = 0; k < 4; k++) {
        split_f32<<<SPC / 256, 256, 0, ss>>>(
            (const float4*)xt + (size_t)k * SPC,
            (uint2*)xhi + (size_t)k * SPC, (uint2*)xlo + (size_t)k * SPC, SPC);
        cudaEventRecord(ev_sp[k], ss);
    }

    // aux: weight packing + combined weights
    pack_w<<<2048, 256, 0, aux>>>(W_x, W_f, W_r, W_cx, b_f, b_r, b_cx);
    cudaEventRecord(ev_pw, aux);
    pack_wxl_t<<<dim3(16, 32), 256, 0, aux>>>(W_xl);
    bias_comb_k<<<256, 256, 0, aux>>>(W_x, W_f, W_r, W_cx, b_xl);
    gemm_tc<1><<<dim3(4, 16), 256, GEMM_SMEM, aux>>>(
        whi, wlo, wxlThi, wxlTlo, bias, nullptr, wchi, wclo, NIN, NOUT, 0);
    cudaEventRecord(ev_w, aux);

    // main: GEMM0 chunks (K=1024), each gated on its split chunk
    cudaStreamWaitEvent(0, ev_pw, 0);
    for (int k = 0; k < 4; k++) {
        cudaStreamWaitEvent(0, ev_sp[k], 0);
        gemm_tc<0><<<dim3(16, 32), 256, GEMM_SMEM>>>(
            xhi, xlo, whi, wlo, bias, Y, nullptr, nullptr, NIN, NBIG, k * MCH);
        cudaEventRecord(ev_g0[k], 0);
    }

    // aux: scan0 chunks (after its weight chain; serial on aux)
    for (int k = 0; k < 4; k++) {
        cudaStreamWaitEvent(aux, ev_g0[k], 0);
        sru_scan_chunk<1><<<128, 128, 0, aux>>>(
            Y, k == 0 ? ctf : cst, cst, nullptr, h1hi, h1lo, k * TCH);
        cudaEventRecord(ev_s0[k], aux);
    }

    // gs: GEMM1 chunks (K=512) — fill GEMM0 tail waves as soon as h1_k ready
    cudaStreamWaitEvent(gs, ev_w, 0);
    for (int k = 0; k < 4; k++) {
        cudaStreamWaitEvent(gs, ev_s0[k], 0);  // h1 chunk ready; Y chunk free
        gemm_tc<0><<<dim3(16, 32), 256, GEMM_SMEM, gs>>>(
            h1hi, h1lo, wchi, wclo, bias2, Y, nullptr, nullptr, NOUT, NBIG,
            k * MCH);
        cudaEventRecord(ev_g1[k], gs);
    }

    // aux: scan1 chunks (serial after scan0 chain on aux)
    for (int k = 0; k < 4; k++) {
        cudaStreamWaitEvent(aux, ev_g1[k], 0);
        sru_scan_chunk<0><<<128, 128, 0, aux>>>(
            Y, k == 0 ? ctf + E_TOT : cst,
            k == 3 ? out + (size_t)M_TOT * NOUT : cst,
            out, nullptr, nullptr, k * TCH);
    }

    // ---- join everything back into the main stream ----
    cudaEventRecord(ev_end, aux);
    cudaStreamWaitEvent(0, ev_end, 0);
}